// round 11
// baseline (speedup 1.0000x reference)
#include <cuda_runtime.h>
#include <cuda_bf16.h>
#include <math.h>
#include <stdint.h>

// Problem constants
#define BATCH   2
#define T_SEQ   2048
#define CDIM    1024
#define NH      16
#define DH      64
#define C3      (3 * CDIM)
#define MROWS   (BATCH * T_SEQ)   // 4096

// ---------------------------------------------------------------------------
// Scratch (device globals — no cudaMalloc allowed)
// ---------------------------------------------------------------------------
__device__ __nv_bfloat16 g_qkvhi[(size_t)MROWS * C3];     // [B*T, 3C]
__device__ __nv_bfloat16 g_qkvlo[(size_t)MROWS * C3];
__device__ __nv_bfloat16 g_xhi[(size_t)MROWS * CDIM];
__device__ __nv_bfloat16 g_xlo[(size_t)MROWS * CDIM];
__device__ __nv_bfloat16 g_wqkvT_hi[(size_t)C3 * CDIM];   // [3072,1024] ([N,K])
__device__ __nv_bfloat16 g_wqkvT_lo[(size_t)C3 * CDIM];
__device__ __nv_bfloat16 g_wprojT_hi[(size_t)CDIM * CDIM];
__device__ __nv_bfloat16 g_wprojT_lo[(size_t)CDIM * CDIM];
__device__ __nv_bfloat16 g_ahi[(size_t)MROWS * CDIM];
__device__ __nv_bfloat16 g_alo[(size_t)MROWS * CDIM];

// ---------------------------------------------------------------------------
// PTX helpers
// ---------------------------------------------------------------------------
__device__ __forceinline__ uint32_t smem_u32(const void* p) {
    uint32_t a;
    asm("{ .reg .u64 t; cvta.to.shared.u64 t, %1; cvt.u32.u64 %0, t; }" : "=r"(a) : "l"(p));
    return a;
}

#define CP_ASYNC16(dst, src)   asm volatile("cp.async.cg.shared.global [%0], [%1], 16;" :: "r"(dst), "l"(src) : "memory")
#define CP_COMMIT()            asm volatile("cp.async.commit_group;" ::: "memory")
#define CP_WAIT(n)             asm volatile("cp.async.wait_group %0;" :: "n"(n) : "memory")

__device__ __forceinline__ void ldsm_x4(uint32_t* r, uint32_t addr) {
    asm volatile("ldmatrix.sync.aligned.m8n8.x4.shared.b16 {%0,%1,%2,%3}, [%4];"
        : "=r"(r[0]), "=r"(r[1]), "=r"(r[2]), "=r"(r[3]) : "r"(addr));
}
__device__ __forceinline__ void ldsm_x4_t(uint32_t* r, uint32_t addr) {
    asm volatile("ldmatrix.sync.aligned.m8n8.x4.trans.shared.b16 {%0,%1,%2,%3}, [%4];"
        : "=r"(r[0]), "=r"(r[1]), "=r"(r[2]), "=r"(r[3]) : "r"(addr));
}
__device__ __forceinline__ void mma_bf16(float* d, const uint32_t* a, const uint32_t* b) {
    asm volatile(
        "mma.sync.aligned.m16n8k16.row.col.f32.bf16.bf16.f32 "
        "{%0,%1,%2,%3}, {%4,%5,%6,%7}, {%8,%9}, {%0,%1,%2,%3};"
        : "+f"(d[0]), "+f"(d[1]), "+f"(d[2]), "+f"(d[3])
        : "r"(a[0]), "r"(a[1]), "r"(a[2]), "r"(a[3]), "r"(b[0]), "r"(b[1]));
}

__device__ __forceinline__ uint32_t pack_hi2(float a, float b) {
    __nv_bfloat162 t = __halves2bfloat162(__float2bfloat16(a), __float2bfloat16(b));
    return *(uint32_t*)&t;
}
__device__ __forceinline__ uint32_t pack_lo2(float a, float b) {
    float ra = a - __bfloat162float(__float2bfloat16(a));
    float rb = b - __bfloat162float(__float2bfloat16(b));
    __nv_bfloat162 t = __halves2bfloat162(__float2bfloat16(ra), __float2bfloat16(rb));
    return *(uint32_t*)&t;
}
__device__ __forceinline__ void store_hilo2(__nv_bfloat16* ph, __nv_bfloat16* pl,
                                            float a, float b) {
    __nv_bfloat16 ha = __float2bfloat16(a), hb = __float2bfloat16(b);
    *(__nv_bfloat162*)ph = __halves2bfloat162(ha, hb);
    *(__nv_bfloat162*)pl = __halves2bfloat162(
        __float2bfloat16(a - __bfloat162float(ha)),
        __float2bfloat16(b - __bfloat162float(hb)));
}

// ---------------------------------------------------------------------------
// Conversion kernels
// ---------------------------------------------------------------------------
__global__ void conv_hilo_kernel(const float* __restrict__ in,
                                 __nv_bfloat16* __restrict__ hi,
                                 __nv_bfloat16* __restrict__ lo, int n4) {
    int i = blockIdx.x * blockDim.x + threadIdx.x;
    if (i >= n4) return;
    float4 v = ((const float4*)in)[i];
    uint32_t* hp = (uint32_t*)hi;
    uint32_t* lp = (uint32_t*)lo;
    hp[2 * i]     = pack_hi2(v.x, v.y);
    hp[2 * i + 1] = pack_hi2(v.z, v.w);
    lp[2 * i]     = pack_lo2(v.x, v.y);
    lp[2 * i + 1] = pack_lo2(v.z, v.w);
}

__global__ void convT_hilo_kernel(const float* __restrict__ in,
                                  __nv_bfloat16* __restrict__ hiT,
                                  __nv_bfloat16* __restrict__ loT, int K, int N) {
    __shared__ float t[32][33];
    int nx = blockIdx.x * 32, ky = blockIdx.y * 32;
    int tx = threadIdx.x, ty = threadIdx.y;   // block (32, 8)
#pragma unroll
    for (int i = 0; i < 4; i++)
        t[ty + i * 8][tx] = in[(size_t)(ky + ty + i * 8) * N + nx + tx];
    __syncthreads();
#pragma unroll
    for (int i = 0; i < 4; i++) {
        float v = t[tx][ty + i * 8];
        int n = nx + ty + i * 8, k = ky + tx;
        __nv_bfloat16 h = __float2bfloat16(v);
        hiT[(size_t)n * K + k] = h;
        loT[(size_t)n * K + k] = __float2bfloat16(v - __bfloat162float(h));
    }
}

// ---------------------------------------------------------------------------
// HMMA bf16x3 GEMM: C = A @ B^T + bias (B as [N,K]).
// mode 0: fp32 out -> Cf.  mode 1: hi/lo bf16 out -> Chi/Clo, cols<qcols scaled 0.125.
// Term-outermost MMA ordering: RAW reuse distance 16 MMAs (was 1).
// ---------------------------------------------------------------------------
#define ROWB      80u
#define OP_BYTES  (128u * ROWB)
#define STG_BYTES (4u * OP_BYTES)
#define GEMM_SMEM (2u * STG_BYTES)    // 81920  (2 CTAs -> 160KB of 227KB)

__device__ __forceinline__ uint32_t a_frag_addr(uint32_t base, int mr, int ks, int lane) {
    int row = mr + (lane & 7) + ((lane >> 3) & 1) * 8;
    int kb  = ks * 32 + (lane >> 4) * 16;
    return base + row * ROWB + kb;
}
__device__ __forceinline__ uint32_t b_frag_addr(uint32_t base, int nr, int ks, int lane) {
    int row = nr + (lane & 7) + (lane >> 4) * 8;
    int kb  = ks * 32 + ((lane >> 3) & 1) * 16;
    return base + row * ROWB + kb;
}

__global__ __launch_bounds__(256, 2)
void gemm_hmma_bf16x3_kernel(const __nv_bfloat16* __restrict__ Ahi, const __nv_bfloat16* __restrict__ Alo,
                             const __nv_bfloat16* __restrict__ Bhi, const __nv_bfloat16* __restrict__ Blo,
                             const float* __restrict__ bias,
                             float* __restrict__ Cf,
                             __nv_bfloat16* __restrict__ Chi, __nv_bfloat16* __restrict__ Clo,
                             int M, int N, int K, int mode, int qcols) {
    extern __shared__ char smem[];
    const uint32_t sb = smem_u32(smem);
    const int tid = threadIdx.x;
    const int lane = tid & 31;
    const int wid = tid >> 5;
    const int wm = (wid & 1) * 64;
    const int wn = (wid >> 1) * 32;
    const int row0 = blockIdx.y * 128, col0 = blockIdx.x * 128;

    const __nv_bfloat16* srcs[4] = {
        Ahi + (size_t)row0 * K, Alo + (size_t)row0 * K,
        Bhi + (size_t)col0 * K, Blo + (size_t)col0 * K };

    const int pos0 = tid, pos1 = tid + 256;
    const int r0l = pos0 >> 2, c0l = pos0 & 3;
    const int r1l = pos1 >> 2, c1l = pos1 & 3;

    float acc[4][4][4];
#pragma unroll
    for (int mt = 0; mt < 4; mt++)
#pragma unroll
        for (int nt = 0; nt < 4; nt++)
#pragma unroll
            for (int e = 0; e < 4; e++) acc[mt][nt][e] = 0.f;

    const int nchunk = K / 32;
    {
        uint32_t st = sb;
#pragma unroll
        for (int op = 0; op < 4; op++) {
            const __nv_bfloat16* s = srcs[op];
            CP_ASYNC16(st + op * OP_BYTES + r0l * ROWB + c0l * 16, s + (size_t)r0l * K + c0l * 8);
            CP_ASYNC16(st + op * OP_BYTES + r1l * ROWB + c1l * 16, s + (size_t)r1l * K + c1l * 8);
        }
        CP_COMMIT();
    }

    for (int ch = 0; ch < nchunk; ch++) {
        if (ch + 1 < nchunk) {
            uint32_t st = sb + ((ch + 1) & 1) * STG_BYTES;
            const int k0 = (ch + 1) * 32;
#pragma unroll
            for (int op = 0; op < 4; op++) {
                const __nv_bfloat16* s = srcs[op];
                CP_ASYNC16(st + op * OP_BYTES + r0l * ROWB + c0l * 16, s + (size_t)r0l * K + k0 + c0l * 8);
                CP_ASYNC16(st + op * OP_BYTES + r1l * ROWB + c1l * 16, s + (size_t)r1l * K + k0 + c1l * 8);
            }
            CP_COMMIT();
            CP_WAIT(1);
        } else {
            CP_WAIT(0);
        }
        __syncthreads();

        const uint32_t st = sb + (ch & 1) * STG_BYTES;
        const uint32_t sAhi = st, sAlo = st + OP_BYTES;
        const uint32_t sBhi = st + 2 * OP_BYTES, sBlo = st + 3 * OP_BYTES;

#pragma unroll
        for (int ks = 0; ks < 2; ks++) {
            uint32_t ah[4][4], al[4][4], bh[2][4], bl[2][4];
#pragma unroll
            for (int mt = 0; mt < 4; mt++) {
                ldsm_x4(ah[mt], a_frag_addr(sAhi, wm + 16 * mt, ks, lane));
                ldsm_x4(al[mt], a_frag_addr(sAlo, wm + 16 * mt, ks, lane));
            }
#pragma unroll
            for (int g = 0; g < 2; g++) {
                ldsm_x4(bh[g], b_frag_addr(sBhi, wn + 16 * g, ks, lane));
                ldsm_x4(bl[g], b_frag_addr(sBlo, wn + 16 * g, ks, lane));
            }
            // term 1: hi*hi  (16 independent accs)
#pragma unroll
            for (int mt = 0; mt < 4; mt++)
#pragma unroll
                for (int g = 0; g < 2; g++) {
                    mma_bf16(acc[mt][2 * g],     ah[mt], &bh[g][0]);
                    mma_bf16(acc[mt][2 * g + 1], ah[mt], &bh[g][2]);
                }
            // term 2: hi*lo
#pragma unroll
            for (int mt = 0; mt < 4; mt++)
#pragma unroll
                for (int g = 0; g < 2; g++) {
                    mma_bf16(acc[mt][2 * g],     ah[mt], &bl[g][0]);
                    mma_bf16(acc[mt][2 * g + 1], ah[mt], &bl[g][2]);
                }
            // term 3: lo*hi
#pragma unroll
            for (int mt = 0; mt < 4; mt++)
#pragma unroll
                for (int g = 0; g < 2; g++) {
                    mma_bf16(acc[mt][2 * g],     al[mt], &bh[g][0]);
                    mma_bf16(acc[mt][2 * g + 1], al[mt], &bh[g][2]);
                }
        }
        __syncthreads();
    }

#pragma unroll
    for (int mt = 0; mt < 4; mt++) {
        int r = row0 + wm + 16 * mt + (lane >> 2);
#pragma unroll
        for (int nt = 0; nt < 4; nt++) {
            int c = col0 + wn + 8 * nt + (lane & 3) * 2;
            float bx = __ldg(&bias[c]), by = __ldg(&bias[c + 1]);
            float x0 = acc[mt][nt][0] + bx, x1 = acc[mt][nt][1] + by;
            float x2 = acc[mt][nt][2] + bx, x3 = acc[mt][nt][3] + by;
            if (mode == 0) {
                float2 v0 = { x0, x1 }, v1 = { x2, x3 };
                *(float2*)&Cf[(size_t)r * N + c]       = v0;
                *(float2*)&Cf[(size_t)(r + 8) * N + c] = v1;
            } else {
                float sc = (c < qcols) ? 0.125f : 1.f;
                store_hilo2(&Chi[(size_t)r * N + c],       &Clo[(size_t)r * N + c],       x0 * sc, x1 * sc);
                store_hilo2(&Chi[(size_t)(r + 8) * N + c], &Clo[(size_t)(r + 8) * N + c], x2 * sc, x3 * sc);
            }
        }
    }
}

// ---------------------------------------------------------------------------
// HMMA flash attention (causal), bf16x3. Block = 128 queries of one (b,h).
// 8 warps x 16 rows; softmax in registers. K/V double-buffered via cp.async.
// MMA streams interleaved across the two n-subtiles to shorten RAW chains.
// ---------------------------------------------------------------------------
#define ROWA       144u               // 64 bf16 = 128B data + 16B pad
#define AQ_BYTES   (128u * ROWA)      // 18432
#define AKV_BYTES  (64u * ROWA)       // 9216
#define ATT_SMEM   (2u * AQ_BYTES + 2u * 4u * AKV_BYTES)   // 110592

__device__ __forceinline__ uint32_t afragA(uint32_t base, int mr, int ks, int lane) {
    int row = mr + (lane & 7) + ((lane >> 3) & 1) * 8;
    int kb  = ks * 32 + (lane >> 4) * 16;
    return base + row * ROWA + kb;
}
__device__ __forceinline__ uint32_t bfragA(uint32_t base, int nr, int ks, int lane) {
    int row = nr + (lane & 7) + (lane >> 4) * 8;
    int kb  = ks * 32 + ((lane >> 3) & 1) * 16;
    return base + row * ROWA + kb;
}
// V (trans) fragment: p covers d-cols 16p..16p+15.
__device__ __forceinline__ uint32_t vfragA(uint32_t base, int ks, int p, int lane) {
    int row = ks * 16 + (lane & 15);
    int col = p * 32 + ((lane >> 4) & 1) * 16;
    return base + row * ROWA + col;
}

__global__ __launch_bounds__(256, 2)
void flash_attn_hmma_kernel(const __nv_bfloat16* __restrict__ qkvhi,
                            const __nv_bfloat16* __restrict__ qkvlo,
                            __nv_bfloat16* __restrict__ ohi,
                            __nv_bfloat16* __restrict__ olo) {
    extern __shared__ char smem[];
    const uint32_t sb = smem_u32(smem);
    const int tid = threadIdx.x, lane = tid & 31, wid = tid >> 5;
    const int bh = blockIdx.y, b = bh >> 4, h = bh & 15;
    const int q0 = blockIdx.x * 128;
    const int wrow = wid * 16;

    const size_t rowbase = (size_t)b * T_SEQ;
    const int qc = h * DH, kc = CDIM + h * DH, vc = 2 * CDIM + h * DH;
    const uint32_t kvb = sb + 2u * AQ_BYTES;

    // Q load (hi+lo): 128 rows x 8 chunks per tensor
#pragma unroll
    for (int t = 0; t < 4; t++) {
        int ci = tid + t * 256;
        int r = ci >> 3, c = ci & 7;
        const size_t grow = (rowbase + q0 + r) * C3 + qc + c * 8;
        CP_ASYNC16(sb + r * ROWA + c * 16,            qkvhi + grow);
        CP_ASYNC16(sb + AQ_BYTES + r * ROWA + c * 16, qkvlo + grow);
    }
    // KV tile 0 into stage 0
    {
        const uint32_t base = kvb;
#pragma unroll
        for (int t = 0; t < 2; t++) {
            int ci = tid + t * 256;
            int r = ci >> 3, c = ci & 7;
            const size_t grow = (rowbase + r) * C3;
            CP_ASYNC16(base + 0 * AKV_BYTES + r * ROWA + c * 16, qkvhi + grow + kc + c * 8);
            CP_ASYNC16(base + 1 * AKV_BYTES + r * ROWA + c * 16, qkvlo + grow + kc + c * 8);
            CP_ASYNC16(base + 2 * AKV_BYTES + r * ROWA + c * 16, qkvhi + grow + vc + c * 8);
            CP_ASYNC16(base + 3 * AKV_BYTES + r * ROWA + c * 16, qkvlo + grow + vc + c * 8);
        }
        CP_COMMIT();
    }

    float m0 = -INFINITY, m1 = -INFINITY, l0 = 0.f, l1 = 0.f;
    float o[8][4];
#pragma unroll
    for (int n = 0; n < 8; n++)
#pragma unroll
        for (int e = 0; e < 4; e++) o[n][e] = 0.f;

    const int ntiles = q0 / 64 + 2;
    for (int kt = 0; kt < ntiles; kt++) {
        __syncthreads();   // all warps done reading the stage we're about to overwrite
        if (kt + 1 < ntiles) {
            const uint32_t base = kvb + ((kt + 1) & 1) * 4u * AKV_BYTES;
            const int k0n = (kt + 1) * 64;
#pragma unroll
            for (int t = 0; t < 2; t++) {
                int ci = tid + t * 256;
                int r = ci >> 3, c = ci & 7;
                const size_t grow = (rowbase + k0n + r) * C3;
                CP_ASYNC16(base + 0 * AKV_BYTES + r * ROWA + c * 16, qkvhi + grow + kc + c * 8);
                CP_ASYNC16(base + 1 * AKV_BYTES + r * ROWA + c * 16, qkvlo + grow + kc + c * 8);
                CP_ASYNC16(base + 2 * AKV_BYTES + r * ROWA + c * 16, qkvhi + grow + vc + c * 8);
                CP_ASYNC16(base + 3 * AKV_BYTES + r * ROWA + c * 16, qkvlo + grow + vc + c * 8);
            }
            CP_COMMIT();
            CP_WAIT(1);
        } else {
            CP_WAIT(0);
        }
        __syncthreads();

        const int k0 = kt * 64;
        const uint32_t stg = kvb + (kt & 1) * 4u * AKV_BYTES;
        const uint32_t sKhi = stg, sKlo = stg + AKV_BYTES;
        const uint32_t sVhi = stg + 2 * AKV_BYTES, sVlo = stg + 3 * AKV_BYTES;

        // ---- S = Q K^T (3-term, interleaved n-subtiles) ----
        float s[8][4];
#pragma unroll
        for (int n = 0; n < 8; n++)
#pragma unroll
            for (int e = 0; e < 4; e++) s[n][e] = 0.f;

#pragma unroll
        for (int ks = 0; ks < 4; ks++) {
            uint32_t qh[4], ql[4];
            ldsm_x4(qh, afragA(sb, wrow, ks, lane));
            ldsm_x4(ql, afragA(sb + AQ_BYTES, wrow, ks, lane));
#pragma unroll
            for (int g = 0; g < 4; g++) {
                uint32_t kh[4], kl[4];
                ldsm_x4(kh, bfragA(sKhi, g * 16, ks, lane));
                ldsm_x4(kl, bfragA(sKlo, g * 16, ks, lane));
                mma_bf16(s[2 * g],     qh, &kh[0]);
                mma_bf16(s[2 * g + 1], qh, &kh[2]);
                mma_bf16(s[2 * g],     qh, &kl[0]);
                mma_bf16(s[2 * g + 1], qh, &kl[2]);
                mma_bf16(s[2 * g],     ql, &kh[0]);
                mma_bf16(s[2 * g + 1], ql, &kh[2]);
            }
        }

        // ---- causal mask ----
        if (k0 + 63 > q0 + wrow) {
            const int r0g = q0 + wrow + (lane >> 2);
#pragma unroll
            for (int n = 0; n < 8; n++) {
                int cg = k0 + n * 8 + (lane & 3) * 2;
#pragma unroll
                for (int e = 0; e < 4; e++) {
                    int rg = r0g + ((e >> 1) << 3);
                    int cc = cg + (e & 1);
                    if (cc > rg) s[n][e] = -INFINITY;
                }
            }
        }

        // ---- online softmax (per-thread rows, quad reduce) ----
        float mx0 = m0, mx1 = m1;
#pragma unroll
        for (int n = 0; n < 8; n++) {
            mx0 = fmaxf(mx0, fmaxf(s[n][0], s[n][1]));
            mx1 = fmaxf(mx1, fmaxf(s[n][2], s[n][3]));
        }
        mx0 = fmaxf(mx0, __shfl_xor_sync(0xffffffffu, mx0, 1));
        mx0 = fmaxf(mx0, __shfl_xor_sync(0xffffffffu, mx0, 2));
        mx1 = fmaxf(mx1, __shfl_xor_sync(0xffffffffu, mx1, 1));
        mx1 = fmaxf(mx1, __shfl_xor_sync(0xffffffffu, mx1, 2));
        float a0 = __expf(m0 - mx0), a1 = __expf(m1 - mx1);
        m0 = mx0; m1 = mx1;

        float sum0 = 0.f, sum1 = 0.f;
#pragma unroll
        for (int n = 0; n < 8; n++) {
            s[n][0] = __expf(s[n][0] - mx0); sum0 += s[n][0];
            s[n][1] = __expf(s[n][1] - mx0); sum0 += s[n][1];
            s[n][2] = __expf(s[n][2] - mx1); sum1 += s[n][2];
            s[n][3] = __expf(s[n][3] - mx1); sum1 += s[n][3];
        }
        sum0 += __shfl_xor_sync(0xffffffffu, sum0, 1);
        sum0 += __shfl_xor_sync(0xffffffffu, sum0, 2);
        sum1 += __shfl_xor_sync(0xffffffffu, sum1, 1);
        sum1 += __shfl_xor_sync(0xffffffffu, sum1, 2);
        l0 = l0 * a0 + sum0;
        l1 = l1 * a1 + sum1;

#pragma unroll
        for (int n = 0; n < 8; n++) {
            o[n][0] *= a0; o[n][1] *= a0;
            o[n][2] *= a1; o[n][3] *= a1;
        }

        // ---- O += P V (3-term, P split in registers, interleaved subtiles) ----
#pragma unroll
        for (int ks = 0; ks < 4; ks++) {
            uint32_t ph[4], pl[4];
            ph[0] = pack_hi2(s[2 * ks][0],     s[2 * ks][1]);
            ph[1] = pack_hi2(s[2 * ks][2],     s[2 * ks][3]);
            ph[2] = pack_hi2(s[2 * ks + 1][0], s[2 * ks + 1][1]);
            ph[3] = pack_hi2(s[2 * ks + 1][2], s[2 * ks + 1][3]);
            pl[0] = pack_lo2(s[2 * ks][0],     s[2 * ks][1]);
            pl[1] = pack_lo2(s[2 * ks][2],     s[2 * ks][3]);
            pl[2] = pack_lo2(s[2 * ks + 1][0], s[2 * ks + 1][1]);
            pl[3] = pack_lo2(s[2 * ks + 1][2], s[2 * ks + 1][3]);
#pragma unroll
            for (int p = 0; p < 4; p++) {
                uint32_t vh[4], vl[4];
                ldsm_x4_t(vh, vfragA(sVhi, ks, p, lane));
                ldsm_x4_t(vl, vfragA(sVlo, ks, p, lane));
                mma_bf16(o[2 * p],     ph, &vh[0]);
                mma_bf16(o[2 * p + 1], ph, &vh[2]);
                mma_bf16(o[2 * p],     ph, &vl[0]);
                mma_bf16(o[2 * p + 1], ph, &vl[2]);
                mma_bf16(o[2 * p],     pl, &vh[0]);
                mma_bf16(o[2 * p + 1], pl, &vh[2]);
            }
        }
    }

    // ---- epilogue: normalize + hi/lo store ----
    const float inv0 = 1.f / l0, inv1 = 1.f / l1;
    const int r0g = q0 + wrow + (lane >> 2);
    const size_t ro0 = (rowbase + r0g) * CDIM + h * DH;
    const size_t ro1 = (rowbase + r0g + 8) * CDIM + h * DH;
#pragma unroll
    for (int n = 0; n < 8; n++) {
        int c = n * 8 + (lane & 3) * 2;
        store_hilo2(&ohi[ro0 + c], &olo[ro0 + c], o[n][0] * inv0, o[n][1] * inv0);
        store_hilo2(&ohi[ro1 + c], &olo[ro1 + c], o[n][2] * inv1, o[n][3] * inv1);
    }
}

// ---------------------------------------------------------------------------
// Launch
// ---------------------------------------------------------------------------
extern "C" void kernel_launch(void* const* d_in, const int* in_sizes, int n_in,
                              void* d_out, int out_size) {
    const float* x      = (const float*)d_in[0];
    const float* w_qkv  = (const float*)d_in[1];
    const float* b_qkv  = (const float*)d_in[2];
    const float* w_proj = (const float*)d_in[3];
    const float* b_proj = (const float*)d_in[4];
    float* out = (float*)d_out;

    __nv_bfloat16 *qkvhi, *qkvlo, *xhi, *xlo, *wqh, *wql, *wph, *wpl, *ahi, *alo;
    cudaGetSymbolAddress((void**)&qkvhi, g_qkvhi);
    cudaGetSymbolAddress((void**)&qkvlo, g_qkvlo);
    cudaGetSymbolAddress((void**)&xhi, g_xhi);
    cudaGetSymbolAddress((void**)&xlo, g_xlo);
    cudaGetSymbolAddress((void**)&wqh, g_wqkvT_hi);
    cudaGetSymbolAddress((void**)&wql, g_wqkvT_lo);
    cudaGetSymbolAddress((void**)&wph, g_wprojT_hi);
    cudaGetSymbolAddress((void**)&wpl, g_wprojT_lo);
    cudaGetSymbolAddress((void**)&ahi, g_ahi);
    cudaGetSymbolAddress((void**)&alo, g_alo);

    cudaFuncSetAttribute(gemm_hmma_bf16x3_kernel,
                         cudaFuncAttributeMaxDynamicSharedMemorySize, (int)GEMM_SMEM);
    cudaFuncSetAttribute(flash_attn_hmma_kernel,
                         cudaFuncAttributeMaxDynamicSharedMemorySize, (int)ATT_SMEM);

    // 0) operand conversion
    {
        int n4 = MROWS * CDIM / 4;
        conv_hilo_kernel<<<(n4 + 255) / 256, 256>>>(x, xhi, xlo, n4);
        dim3 blk(32, 8);
        convT_hilo_kernel<<<dim3(C3 / 32, CDIM / 32), blk>>>(w_qkv, wqh, wql, CDIM, C3);
        convT_hilo_kernel<<<dim3(CDIM / 32, CDIM / 32), blk>>>(w_proj, wph, wpl, CDIM, CDIM);
    }

    // 1) QKV projection -> bf16 hi/lo (Q pre-scaled by 0.125)
    gemm_hmma_bf16x3_kernel<<<dim3(C3 / 128, MROWS / 128), 256, GEMM_SMEM>>>(
        xhi, xlo, wqh, wql, b_qkv, nullptr, qkvhi, qkvlo, MROWS, C3, CDIM, 1, CDIM);

    // 2) HMMA flash attention -> bf16 hi/lo
    flash_attn_hmma_kernel<<<dim3(T_SEQ / 128, BATCH * NH), 256, ATT_SMEM>>>(
        qkvhi, qkvlo, ahi, alo);

    // 3) Output projection -> fp32 d_out
    gemm_hmma_bf16x3_kernel<<<dim3(CDIM / 128, MROWS / 128), 256, GEMM_SMEM>>>(
        ahi, alo, wph, wpl, b_proj, out, nullptr, nullptr, MROWS, CDIM, CDIM, 0, 0);
}

// round 12
// speedup vs baseline: 1.0251x; 1.0251x over previous
#include <cuda_runtime.h>
#include <cuda_bf16.h>
#include <math.h>
#include <stdint.h>

// Problem constants
#define BATCH   2
#define T_SEQ   2048
#define CDIM    1024
#define NH      16
#define DH      64
#define C3      (3 * CDIM)
#define MROWS   (BATCH * T_SEQ)   // 4096

// Q pre-scale: (1/sqrt(64)) * log2(e)  -> softmax uses ex2 directly
#define QSCALE  0.18033688011112042f

// ---------------------------------------------------------------------------
// Scratch (device globals — no cudaMalloc allowed)
// ---------------------------------------------------------------------------
__device__ __nv_bfloat16 g_qkvhi[(size_t)MROWS * C3];     // [B*T, 3C]
__device__ __nv_bfloat16 g_qkvlo[(size_t)MROWS * C3];
__device__ __nv_bfloat16 g_xhi[(size_t)MROWS * CDIM];
__device__ __nv_bfloat16 g_xlo[(size_t)MROWS * CDIM];
__device__ __nv_bfloat16 g_wqkvT_hi[(size_t)C3 * CDIM];   // [3072,1024] ([N,K])
__device__ __nv_bfloat16 g_wqkvT_lo[(size_t)C3 * CDIM];
__device__ __nv_bfloat16 g_wprojT_hi[(size_t)CDIM * CDIM];
__device__ __nv_bfloat16 g_wprojT_lo[(size_t)CDIM * CDIM];
__device__ __nv_bfloat16 g_ahi[(size_t)MROWS * CDIM];
__device__ __nv_bfloat16 g_alo[(size_t)MROWS * CDIM];

// ---------------------------------------------------------------------------
// PTX helpers
// ---------------------------------------------------------------------------
__device__ __forceinline__ uint32_t smem_u32(const void* p) {
    uint32_t a;
    asm("{ .reg .u64 t; cvta.to.shared.u64 t, %1; cvt.u32.u64 %0, t; }" : "=r"(a) : "l"(p));
    return a;
}

#define CP_ASYNC16(dst, src)   asm volatile("cp.async.cg.shared.global [%0], [%1], 16;" :: "r"(dst), "l"(src) : "memory")
#define CP_COMMIT()            asm volatile("cp.async.commit_group;" ::: "memory")
#define CP_WAIT(n)             asm volatile("cp.async.wait_group %0;" :: "n"(n) : "memory")

__device__ __forceinline__ void ldsm_x4(uint32_t* r, uint32_t addr) {
    asm volatile("ldmatrix.sync.aligned.m8n8.x4.shared.b16 {%0,%1,%2,%3}, [%4];"
        : "=r"(r[0]), "=r"(r[1]), "=r"(r[2]), "=r"(r[3]) : "r"(addr));
}
__device__ __forceinline__ void ldsm_x4_t(uint32_t* r, uint32_t addr) {
    asm volatile("ldmatrix.sync.aligned.m8n8.x4.trans.shared.b16 {%0,%1,%2,%3}, [%4];"
        : "=r"(r[0]), "=r"(r[1]), "=r"(r[2]), "=r"(r[3]) : "r"(addr));
}
__device__ __forceinline__ void mma_bf16(float* d, const uint32_t* a, const uint32_t* b) {
    asm volatile(
        "mma.sync.aligned.m16n8k16.row.col.f32.bf16.bf16.f32 "
        "{%0,%1,%2,%3}, {%4,%5,%6,%7}, {%8,%9}, {%0,%1,%2,%3};"
        : "+f"(d[0]), "+f"(d[1]), "+f"(d[2]), "+f"(d[3])
        : "r"(a[0]), "r"(a[1]), "r"(a[2]), "r"(a[3]), "r"(b[0]), "r"(b[1]));
}

__device__ __forceinline__ float ex2f(float x) {
    float r;
    asm("ex2.approx.f32 %0, %1;" : "=f"(r) : "f"(x));
    return r;
}

// PRMT-based bf16 hi/lo split (truncation): hi = top16 bits (exact repr),
// lo = bf16_trunc(x - hi). Residual error <= 2^-16 |x| -> well inside budget.
__device__ __forceinline__ uint32_t prmt7632(uint32_t a, uint32_t b) {
    uint32_t r;
    asm("prmt.b32 %0, %1, %2, 0x7632;" : "=r"(r) : "r"(a), "r"(b));
    return r;
}
__device__ __forceinline__ uint32_t pack_hi2(float a, float b) {
    return prmt7632(__float_as_uint(a), __float_as_uint(b));
}
__device__ __forceinline__ uint32_t pack_lo2(float a, float b) {
    float ra = a - __uint_as_float(__float_as_uint(a) & 0xFFFF0000u);
    float rb = b - __uint_as_float(__float_as_uint(b) & 0xFFFF0000u);
    return prmt7632(__float_as_uint(ra), __float_as_uint(rb));
}
__device__ __forceinline__ void store_hilo2(__nv_bfloat16* ph, __nv_bfloat16* pl,
                                            float a, float b) {
    *(uint32_t*)ph = pack_hi2(a, b);
    *(uint32_t*)pl = pack_lo2(a, b);
}

// ---------------------------------------------------------------------------
// Conversion kernels
// ---------------------------------------------------------------------------
__global__ void conv_hilo_kernel(const float* __restrict__ in,
                                 __nv_bfloat16* __restrict__ hi,
                                 __nv_bfloat16* __restrict__ lo, int n4) {
    int i = blockIdx.x * blockDim.x + threadIdx.x;
    if (i >= n4) return;
    float4 v = ((const float4*)in)[i];
    uint32_t* hp = (uint32_t*)hi;
    uint32_t* lp = (uint32_t*)lo;
    hp[2 * i]     = pack_hi2(v.x, v.y);
    hp[2 * i + 1] = pack_hi2(v.z, v.w);
    lp[2 * i]     = pack_lo2(v.x, v.y);
    lp[2 * i + 1] = pack_lo2(v.z, v.w);
}

__global__ void convT_hilo_kernel(const float* __restrict__ in,
                                  __nv_bfloat16* __restrict__ hiT,
                                  __nv_bfloat16* __restrict__ loT, int K, int N) {
    __shared__ float t[32][33];
    int nx = blockIdx.x * 32, ky = blockIdx.y * 32;
    int tx = threadIdx.x, ty = threadIdx.y;   // block (32, 8)
#pragma unroll
    for (int i = 0; i < 4; i++)
        t[ty + i * 8][tx] = in[(size_t)(ky + ty + i * 8) * N + nx + tx];
    __syncthreads();
#pragma unroll
    for (int i = 0; i < 4; i++) {
        float v = t[tx][ty + i * 8];
        int n = nx + ty + i * 8, k = ky + tx;
        uint32_t bits = __float_as_uint(v);
        float hf = __uint_as_float(bits & 0xFFFF0000u);
        float lf = v - hf;
        ((uint16_t*)hiT)[(size_t)n * K + k] = (uint16_t)(bits >> 16);
        ((uint16_t*)loT)[(size_t)n * K + k] = (uint16_t)(__float_as_uint(lf) >> 16);
    }
}

// ---------------------------------------------------------------------------
// HMMA bf16x3 GEMM: C = A @ B^T + bias (B as [N,K]).
// mode 0: fp32 out -> Cf.  mode 1: hi/lo bf16 out -> Chi/Clo, cols<qcols scaled QSCALE.
// At the mma.sync issue ceiling (~630 TF/s measured).
// ---------------------------------------------------------------------------
#define ROWB      80u
#define OP_BYTES  (128u * ROWB)
#define STG_BYTES (4u * OP_BYTES)
#define GEMM_SMEM (2u * STG_BYTES)    // 81920  (2 CTAs -> 160KB of 227KB)

__device__ __forceinline__ uint32_t a_frag_addr(uint32_t base, int mr, int ks, int lane) {
    int row = mr + (lane & 7) + ((lane >> 3) & 1) * 8;
    int kb  = ks * 32 + (lane >> 4) * 16;
    return base + row * ROWB + kb;
}
__device__ __forceinline__ uint32_t b_frag_addr(uint32_t base, int nr, int ks, int lane) {
    int row = nr + (lane & 7) + (lane >> 4) * 8;
    int kb  = ks * 32 + ((lane >> 3) & 1) * 16;
    return base + row * ROWB + kb;
}

__global__ __launch_bounds__(256, 2)
void gemm_hmma_bf16x3_kernel(const __nv_bfloat16* __restrict__ Ahi, const __nv_bfloat16* __restrict__ Alo,
                             const __nv_bfloat16* __restrict__ Bhi, const __nv_bfloat16* __restrict__ Blo,
                             const float* __restrict__ bias,
                             float* __restrict__ Cf,
                             __nv_bfloat16* __restrict__ Chi, __nv_bfloat16* __restrict__ Clo,
                             int M, int N, int K, int mode, int qcols) {
    extern __shared__ char smem[];
    const uint32_t sb = smem_u32(smem);
    const int tid = threadIdx.x;
    const int lane = tid & 31;
    const int wid = tid >> 5;
    const int wm = (wid & 1) * 64;
    const int wn = (wid >> 1) * 32;
    const int row0 = blockIdx.y * 128, col0 = blockIdx.x * 128;

    const __nv_bfloat16* srcs[4] = {
        Ahi + (size_t)row0 * K, Alo + (size_t)row0 * K,
        Bhi + (size_t)col0 * K, Blo + (size_t)col0 * K };

    const int pos0 = tid, pos1 = tid + 256;
    const int r0l = pos0 >> 2, c0l = pos0 & 3;
    const int r1l = pos1 >> 2, c1l = pos1 & 3;

    float acc[4][4][4];
#pragma unroll
    for (int mt = 0; mt < 4; mt++)
#pragma unroll
        for (int nt = 0; nt < 4; nt++)
#pragma unroll
            for (int e = 0; e < 4; e++) acc[mt][nt][e] = 0.f;

    const int nchunk = K / 32;
    {
        uint32_t st = sb;
#pragma unroll
        for (int op = 0; op < 4; op++) {
            const __nv_bfloat16* s = srcs[op];
            CP_ASYNC16(st + op * OP_BYTES + r0l * ROWB + c0l * 16, s + (size_t)r0l * K + c0l * 8);
            CP_ASYNC16(st + op * OP_BYTES + r1l * ROWB + c1l * 16, s + (size_t)r1l * K + c1l * 8);
        }
        CP_COMMIT();
    }

    for (int ch = 0; ch < nchunk; ch++) {
        if (ch + 1 < nchunk) {
            uint32_t st = sb + ((ch + 1) & 1) * STG_BYTES;
            const int k0 = (ch + 1) * 32;
#pragma unroll
            for (int op = 0; op < 4; op++) {
                const __nv_bfloat16* s = srcs[op];
                CP_ASYNC16(st + op * OP_BYTES + r0l * ROWB + c0l * 16, s + (size_t)r0l * K + k0 + c0l * 8);
                CP_ASYNC16(st + op * OP_BYTES + r1l * ROWB + c1l * 16, s + (size_t)r1l * K + k0 + c1l * 8);
            }
            CP_COMMIT();
            CP_WAIT(1);
        } else {
            CP_WAIT(0);
        }
        __syncthreads();

        const uint32_t st = sb + (ch & 1) * STG_BYTES;
        const uint32_t sAhi = st, sAlo = st + OP_BYTES;
        const uint32_t sBhi = st + 2 * OP_BYTES, sBlo = st + 3 * OP_BYTES;

#pragma unroll
        for (int ks = 0; ks < 2; ks++) {
            uint32_t ah[4][4], al[4][4], bh[2][4], bl[2][4];
#pragma unroll
            for (int mt = 0; mt < 4; mt++) {
                ldsm_x4(ah[mt], a_frag_addr(sAhi, wm + 16 * mt, ks, lane));
                ldsm_x4(al[mt], a_frag_addr(sAlo, wm + 16 * mt, ks, lane));
            }
#pragma unroll
            for (int g = 0; g < 2; g++) {
                ldsm_x4(bh[g], b_frag_addr(sBhi, wn + 16 * g, ks, lane));
                ldsm_x4(bl[g], b_frag_addr(sBlo, wn + 16 * g, ks, lane));
            }
#pragma unroll
            for (int mt = 0; mt < 4; mt++)
#pragma unroll
                for (int g = 0; g < 2; g++) {
                    mma_bf16(acc[mt][2 * g],     ah[mt], &bh[g][0]);
                    mma_bf16(acc[mt][2 * g + 1], ah[mt], &bh[g][2]);
                }
#pragma unroll
            for (int mt = 0; mt < 4; mt++)
#pragma unroll
                for (int g = 0; g < 2; g++) {
                    mma_bf16(acc[mt][2 * g],     ah[mt], &bl[g][0]);
                    mma_bf16(acc[mt][2 * g + 1], ah[mt], &bl[g][2]);
                }
#pragma unroll
            for (int mt = 0; mt < 4; mt++)
#pragma unroll
                for (int g = 0; g < 2; g++) {
                    mma_bf16(acc[mt][2 * g],     al[mt], &bh[g][0]);
                    mma_bf16(acc[mt][2 * g + 1], al[mt], &bh[g][2]);
                }
        }
        __syncthreads();
    }

#pragma unroll
    for (int mt = 0; mt < 4; mt++) {
        int r = row0 + wm + 16 * mt + (lane >> 2);
#pragma unroll
        for (int nt = 0; nt < 4; nt++) {
            int c = col0 + wn + 8 * nt + (lane & 3) * 2;
            float bx = __ldg(&bias[c]), by = __ldg(&bias[c + 1]);
            float x0 = acc[mt][nt][0] + bx, x1 = acc[mt][nt][1] + by;
            float x2 = acc[mt][nt][2] + bx, x3 = acc[mt][nt][3] + by;
            if (mode == 0) {
                float2 v0 = { x0, x1 }, v1 = { x2, x3 };
                *(float2*)&Cf[(size_t)r * N + c]       = v0;
                *(float2*)&Cf[(size_t)(r + 8) * N + c] = v1;
            } else {
                float sc = (c < qcols) ? QSCALE : 1.f;
                store_hilo2(&Chi[(size_t)r * N + c],       &Clo[(size_t)r * N + c],       x0 * sc, x1 * sc);
                store_hilo2(&Chi[(size_t)(r + 8) * N + c], &Clo[(size_t)(r + 8) * N + c], x2 * sc, x3 * sc);
            }
        }
    }
}

// ---------------------------------------------------------------------------
// HMMA flash attention (causal), bf16x3. Block = 128 queries of one (b,h).
// Heavy-first q ordering (largest q0 launches first). Softmax in log2 domain
// (Q pre-scaled by 0.125*log2e; ex2.approx).
// ---------------------------------------------------------------------------
#define ROWA       144u               // 64 bf16 = 128B data + 16B pad
#define AQ_BYTES   (128u * ROWA)      // 18432
#define AKV_BYTES  (64u * ROWA)       // 9216
#define ATT_SMEM   (2u * AQ_BYTES + 2u * 4u * AKV_BYTES)   // 110592

__device__ __forceinline__ uint32_t afragA(uint32_t base, int mr, int ks, int lane) {
    int row = mr + (lane & 7) + ((lane >> 3) & 1) * 8;
    int kb  = ks * 32 + (lane >> 4) * 16;
    return base + row * ROWA + kb;
}
__device__ __forceinline__ uint32_t bfragA(uint32_t base, int nr, int ks, int lane) {
    int row = nr + (lane & 7) + (lane >> 4) * 8;
    int kb  = ks * 32 + ((lane >> 3) & 1) * 16;
    return base + row * ROWA + kb;
}
// V (trans) fragment: p covers d-cols 16p..16p+15.
__device__ __forceinline__ uint32_t vfragA(uint32_t base, int ks, int p, int lane) {
    int row = ks * 16 + (lane & 15);
    int col = p * 32 + ((lane >> 4) & 1) * 16;
    return base + row * ROWA + col;
}

__global__ __launch_bounds__(256, 2)
void flash_attn_hmma_kernel(const __nv_bfloat16* __restrict__ qkvhi,
                            const __nv_bfloat16* __restrict__ qkvlo,
                            __nv_bfloat16* __restrict__ ohi,
                            __nv_bfloat16* __restrict__ olo) {
    extern __shared__ char smem[];
    const uint32_t sb = smem_u32(smem);
    const int tid = threadIdx.x, lane = tid & 31, wid = tid >> 5;
    const int bh = blockIdx.y, b = bh >> 4, h = bh & 15;
    const int q0 = (gridDim.x - 1 - blockIdx.x) * 128;   // heavy-first
    const int wrow = wid * 16;

    const size_t rowbase = (size_t)b * T_SEQ;
    const int qc = h * DH, kc = CDIM + h * DH, vc = 2 * CDIM + h * DH;
    const uint32_t kvb = sb + 2u * AQ_BYTES;

    // Q load (hi+lo): 128 rows x 8 chunks per tensor
#pragma unroll
    for (int t = 0; t < 4; t++) {
        int ci = tid + t * 256;
        int r = ci >> 3, c = ci & 7;
        const size_t grow = (rowbase + q0 + r) * C3 + qc + c * 8;
        CP_ASYNC16(sb + r * ROWA + c * 16,            qkvhi + grow);
        CP_ASYNC16(sb + AQ_BYTES + r * ROWA + c * 16, qkvlo + grow);
    }
    // KV tile 0 into stage 0
    {
        const uint32_t base = kvb;
#pragma unroll
        for (int t = 0; t < 2; t++) {
            int ci = tid + t * 256;
            int r = ci >> 3, c = ci & 7;
            const size_t grow = (rowbase + r) * C3;
            CP_ASYNC16(base + 0 * AKV_BYTES + r * ROWA + c * 16, qkvhi + grow + kc + c * 8);
            CP_ASYNC16(base + 1 * AKV_BYTES + r * ROWA + c * 16, qkvlo + grow + kc + c * 8);
            CP_ASYNC16(base + 2 * AKV_BYTES + r * ROWA + c * 16, qkvhi + grow + vc + c * 8);
            CP_ASYNC16(base + 3 * AKV_BYTES + r * ROWA + c * 16, qkvlo + grow + vc + c * 8);
        }
        CP_COMMIT();
    }

    float m0 = -INFINITY, m1 = -INFINITY, l0 = 0.f, l1 = 0.f;
    float o[8][4];
#pragma unroll
    for (int n = 0; n < 8; n++)
#pragma unroll
        for (int e = 0; e < 4; e++) o[n][e] = 0.f;

    const int ntiles = q0 / 64 + 2;
    for (int kt = 0; kt < ntiles; kt++) {
        __syncthreads();   // all warps done reading the stage we're about to overwrite
        if (kt + 1 < ntiles) {
            const uint32_t base = kvb + ((kt + 1) & 1) * 4u * AKV_BYTES;
            const int k0n = (kt + 1) * 64;
#pragma unroll
            for (int t = 0; t < 2; t++) {
                int ci = tid + t * 256;
                int r = ci >> 3, c = ci & 7;
                const size_t grow = (rowbase + k0n + r) * C3;
                CP_ASYNC16(base + 0 * AKV_BYTES + r * ROWA + c * 16, qkvhi + grow + kc + c * 8);
                CP_ASYNC16(base + 1 * AKV_BYTES + r * ROWA + c * 16, qkvlo + grow + kc + c * 8);
                CP_ASYNC16(base + 2 * AKV_BYTES + r * ROWA + c * 16, qkvhi + grow + vc + c * 8);
                CP_ASYNC16(base + 3 * AKV_BYTES + r * ROWA + c * 16, qkvlo + grow + vc + c * 8);
            }
            CP_COMMIT();
            CP_WAIT(1);
        } else {
            CP_WAIT(0);
        }
        __syncthreads();

        const int k0 = kt * 64;
        const uint32_t stg = kvb + (kt & 1) * 4u * AKV_BYTES;
        const uint32_t sKhi = stg, sKlo = stg + AKV_BYTES;
        const uint32_t sVhi = stg + 2 * AKV_BYTES, sVlo = stg + 3 * AKV_BYTES;

        // ---- S = Q K^T (3-term, log2 domain) ----
        float s[8][4];
#pragma unroll
        for (int n = 0; n < 8; n++)
#pragma unroll
            for (int e = 0; e < 4; e++) s[n][e] = 0.f;

#pragma unroll
        for (int ks = 0; ks < 4; ks++) {
            uint32_t qh[4], ql[4];
            ldsm_x4(qh, afragA(sb, wrow, ks, lane));
            ldsm_x4(ql, afragA(sb + AQ_BYTES, wrow, ks, lane));
#pragma unroll
            for (int g = 0; g < 4; g++) {
                uint32_t kh[4], kl[4];
                ldsm_x4(kh, bfragA(sKhi, g * 16, ks, lane));
                ldsm_x4(kl, bfragA(sKlo, g * 16, ks, lane));
                mma_bf16(s[2 * g],     qh, &kh[0]);
                mma_bf16(s[2 * g + 1], qh, &kh[2]);
                mma_bf16(s[2 * g],     qh, &kl[0]);
                mma_bf16(s[2 * g + 1], qh, &kl[2]);
                mma_bf16(s[2 * g],     ql, &kh[0]);
                mma_bf16(s[2 * g + 1], ql, &kh[2]);
            }
        }

        // ---- causal mask ----
        if (k0 + 63 > q0 + wrow) {
            const int r0g = q0 + wrow + (lane >> 2);
#pragma unroll
            for (int n = 0; n < 8; n++) {
                int cg = k0 + n * 8 + (lane & 3) * 2;
#pragma unroll
                for (int e = 0; e < 4; e++) {
                    int rg = r0g + ((e >> 1) << 3);
                    int cc = cg + (e & 1);
                    if (cc > rg) s[n][e] = -INFINITY;
                }
            }
        }

        // ---- online softmax (log2 domain, ex2) ----
        float mx0 = m0, mx1 = m1;
#pragma unroll
        for (int n = 0; n < 8; n++) {
            mx0 = fmaxf(mx0, fmaxf(s[n][0], s[n][1]));
            mx1 = fmaxf(mx1, fmaxf(s[n][2], s[n][3]));
        }
        mx0 = fmaxf(mx0, __shfl_xor_sync(0xffffffffu, mx0, 1));
        mx0 = fmaxf(mx0, __shfl_xor_sync(0xffffffffu, mx0, 2));
        mx1 = fmaxf(mx1, __shfl_xor_sync(0xffffffffu, mx1, 1));
        mx1 = fmaxf(mx1, __shfl_xor_sync(0xffffffffu, mx1, 2));
        float a0 = ex2f(m0 - mx0), a1 = ex2f(m1 - mx1);
        m0 = mx0; m1 = mx1;

        float sum0 = 0.f, sum1 = 0.f;
#pragma unroll
        for (int n = 0; n < 8; n++) {
            s[n][0] = ex2f(s[n][0] - mx0); sum0 += s[n][0];
            s[n][1] = ex2f(s[n][1] - mx0); sum0 += s[n][1];
            s[n][2] = ex2f(s[n][2] - mx1); sum1 += s[n][2];
            s[n][3] = ex2f(s[n][3] - mx1); sum1 += s[n][3];
        }
        sum0 += __shfl_xor_sync(0xffffffffu, sum0, 1);
        sum0 += __shfl_xor_sync(0xffffffffu, sum0, 2);
        sum1 += __shfl_xor_sync(0xffffffffu, sum1, 1);
        sum1 += __shfl_xor_sync(0xffffffffu, sum1, 2);
        l0 = l0 * a0 + sum0;
        l1 = l1 * a1 + sum1;

#pragma unroll
        for (int n = 0; n < 8; n++) {
            o[n][0] *= a0; o[n][1] *= a0;
            o[n][2] *= a1; o[n][3] *= a1;
        }

        // ---- O += P V (3-term, P split via PRMT, interleaved subtiles) ----
#pragma unroll
        for (int ks = 0; ks < 4; ks++) {
            uint32_t ph[4], pl[4];
            ph[0] = pack_hi2(s[2 * ks][0],     s[2 * ks][1]);
            ph[1] = pack_hi2(s[2 * ks][2],     s[2 * ks][3]);
            ph[2] = pack_hi2(s[2 * ks + 1][0], s[2 * ks + 1][1]);
            ph[3] = pack_hi2(s[2 * ks + 1][2], s[2 * ks + 1][3]);
            pl[0] = pack_lo2(s[2 * ks][0],     s[2 * ks][1]);
            pl[1] = pack_lo2(s[2 * ks][2],     s[2 * ks][3]);
            pl[2] = pack_lo2(s[2 * ks + 1][0], s[2 * ks + 1][1]);
            pl[3] = pack_lo2(s[2 * ks + 1][2], s[2 * ks + 1][3]);
#pragma unroll
            for (int p = 0; p < 4; p++) {
                uint32_t vh[4], vl[4];
                ldsm_x4_t(vh, vfragA(sVhi, ks, p, lane));
                ldsm_x4_t(vl, vfragA(sVlo, ks, p, lane));
                mma_bf16(o[2 * p],     ph, &vh[0]);
                mma_bf16(o[2 * p + 1], ph, &vh[2]);
                mma_bf16(o[2 * p],     ph, &vl[0]);
                mma_bf16(o[2 * p + 1], ph, &vl[2]);
                mma_bf16(o[2 * p],     pl, &vh[0]);
                mma_bf16(o[2 * p + 1], pl, &vh[2]);
            }
        }
    }

    // ---- epilogue: normalize + hi/lo store ----
    const float inv0 = 1.f / l0, inv1 = 1.f / l1;
    const int r0g = q0 + wrow + (lane >> 2);
    const size_t ro0 = (rowbase + r0g) * CDIM + h * DH;
    const size_t ro1 = (rowbase + r0g + 8) * CDIM + h * DH;
#pragma unroll
    for (int n = 0; n < 8; n++) {
        int c = n * 8 + (lane & 3) * 2;
        store_hilo2(&ohi[ro0 + c], &olo[ro0 + c], o[n][0] * inv0, o[n][1] * inv0);
        store_hilo2(&ohi[ro1 + c], &olo[ro1 + c], o[n][2] * inv1, o[n][3] * inv1);
    }
}

// ---------------------------------------------------------------------------
// Launch
// ---------------------------------------------------------------------------
extern "C" void kernel_launch(void* const* d_in, const int* in_sizes, int n_in,
                              void* d_out, int out_size) {
    const float* x      = (const float*)d_in[0];
    const float* w_qkv  = (const float*)d_in[1];
    const float* b_qkv  = (const float*)d_in[2];
    const float* w_proj = (const float*)d_in[3];
    const float* b_proj = (const float*)d_in[4];
    float* out = (float*)d_out;

    __nv_bfloat16 *qkvhi, *qkvlo, *xhi, *xlo, *wqh, *wql, *wph, *wpl, *ahi, *alo;
    cudaGetSymbolAddress((void**)&qkvhi, g_qkvhi);
    cudaGetSymbolAddress((void**)&qkvlo, g_qkvlo);
    cudaGetSymbolAddress((void**)&xhi, g_xhi);
    cudaGetSymbolAddress((void**)&xlo, g_xlo);
    cudaGetSymbolAddress((void**)&wqh, g_wqkvT_hi);
    cudaGetSymbolAddress((void**)&wql, g_wqkvT_lo);
    cudaGetSymbolAddress((void**)&wph, g_wprojT_hi);
    cudaGetSymbolAddress((void**)&wpl, g_wprojT_lo);
    cudaGetSymbolAddress((void**)&ahi, g_ahi);
    cudaGetSymbolAddress((void**)&alo, g_alo);

    cudaFuncSetAttribute(gemm_hmma_bf16x3_kernel,
                         cudaFuncAttributeMaxDynamicSharedMemorySize, (int)GEMM_SMEM);
    cudaFuncSetAttribute(flash_attn_hmma_kernel,
                         cudaFuncAttributeMaxDynamicSharedMemorySize, (int)ATT_SMEM);

    // 0) operand conversion
    {
        int n4 = MROWS * CDIM / 4;
        conv_hilo_kernel<<<(n4 + 255) / 256, 256>>>(x, xhi, xlo, n4);
        dim3 blk(32, 8);
        convT_hilo_kernel<<<dim3(C3 / 32, CDIM / 32), blk>>>(w_qkv, wqh, wql, CDIM, C3);
        convT_hilo_kernel<<<dim3(CDIM / 32, CDIM / 32), blk>>>(w_proj, wph, wpl, CDIM, CDIM);
    }

    // 1) QKV projection -> bf16 hi/lo (Q pre-scaled by 0.125*log2e)
    gemm_hmma_bf16x3_kernel<<<dim3(C3 / 128, MROWS / 128), 256, GEMM_SMEM>>>(
        xhi, xlo, wqh, wql, b_qkv, nullptr, qkvhi, qkvlo, MROWS, C3, CDIM, 1, CDIM);

    // 2) HMMA flash attention -> bf16 hi/lo
    flash_attn_hmma_kernel<<<dim3(T_SEQ / 128, BATCH * NH), 256, ATT_SMEM>>>(
        qkvhi, qkvlo, ahi, alo);

    // 3) Output projection -> fp32 d_out
    gemm_hmma_bf16x3_kernel<<<dim3(CDIM / 128, MROWS / 128), 256, GEMM_SMEM>>>(
        ahi, alo, wph, wpl, b_proj, out, nullptr, nullptr, MROWS, CDIM, CDIM, 0, 0);
}

// round 15
// speedup vs baseline: 2.2091x; 2.1549x over previous
#include <cuda_runtime.h>
#include <cuda_fp16.h>
#include <math.h>
#include <stdint.h>

// Problem constants
#define BATCH   2
#define T_SEQ   2048
#define CDIM    1024
#define NH      16
#define DH      64
#define C3      (3 * CDIM)
#define MROWS   (BATCH * T_SEQ)   // 4096

// Q pre-scale: (1/sqrt(64)) * log2(e)  -> softmax uses ex2 directly
#define QSCALE  0.18033688011112042f

// ---------------------------------------------------------------------------
// Scratch (device globals — no cudaMalloc allowed)
// ---------------------------------------------------------------------------
__device__ __half g_qkv16 [(size_t)MROWS * C3];    // [B*T, 3C]
__device__ __half g_x16   [(size_t)MROWS * CDIM];
__device__ __half g_wqkvT [(size_t)C3 * CDIM];     // [3072,1024] ([N,K])
__device__ __half g_wprojT[(size_t)CDIM * CDIM];
__device__ __half g_attn16[(size_t)MROWS * CDIM];

// ---------------------------------------------------------------------------
// PTX helpers
// ---------------------------------------------------------------------------
__device__ __forceinline__ uint32_t smem_u32(const void* p) {
    uint32_t a;
    asm("{ .reg .u64 t; cvta.to.shared.u64 t, %1; cvt.u32.u64 %0, t; }" : "=r"(a) : "l"(p));
    return a;
}

#define CP_ASYNC16(dst, src)   asm volatile("cp.async.cg.shared.global [%0], [%1], 16;" :: "r"(dst), "l"(src) : "memory")
#define CP_COMMIT()            asm volatile("cp.async.commit_group;" ::: "memory")
#define CP_WAIT(n)             asm volatile("cp.async.wait_group %0;" :: "n"(n) : "memory")

__device__ __forceinline__ void ldsm_x4(uint32_t* r, uint32_t addr) {
    asm volatile("ldmatrix.sync.aligned.m8n8.x4.shared.b16 {%0,%1,%2,%3}, [%4];"
        : "=r"(r[0]), "=r"(r[1]), "=r"(r[2]), "=r"(r[3]) : "r"(addr));
}
__device__ __forceinline__ void ldsm_x4_t(uint32_t* r, uint32_t addr) {
    asm volatile("ldmatrix.sync.aligned.m8n8.x4.trans.shared.b16 {%0,%1,%2,%3}, [%4];"
        : "=r"(r[0]), "=r"(r[1]), "=r"(r[2]), "=r"(r[3]) : "r"(addr));
}
__device__ __forceinline__ void mma_f16(float* d, const uint32_t* a, const uint32_t* b) {
    asm volatile(
        "mma.sync.aligned.m16n8k16.row.col.f32.f16.f16.f32 "
        "{%0,%1,%2,%3}, {%4,%5,%6,%7}, {%8,%9}, {%0,%1,%2,%3};"
        : "+f"(d[0]), "+f"(d[1]), "+f"(d[2]), "+f"(d[3])
        : "r"(a[0]), "r"(a[1]), "r"(a[2]), "r"(a[3]), "r"(b[0]), "r"(b[1]));
}

__device__ __forceinline__ float ex2f(float x) {
    float r;
    asm("ex2.approx.f32 %0, %1;" : "=f"(r) : "f"(x));
    return r;
}
// pack two fp32 -> fp16x2, low half = a, high half = b (RN)
__device__ __forceinline__ uint32_t pack_f16x2(float a, float b) {
    uint32_t r;
    asm("cvt.rn.f16x2.f32 %0, %1, %2;" : "=r"(r) : "f"(b), "f"(a));
    return r;
}

// ---------------------------------------------------------------------------
// Conversion kernels (fp32 -> fp16)
// ---------------------------------------------------------------------------
__global__ void conv_f16_kernel(const float* __restrict__ in,
                                __half* __restrict__ out, int n4) {
    int i = blockIdx.x * blockDim.x + threadIdx.x;
    if (i >= n4) return;
    float4 v = ((const float4*)in)[i];
    uint32_t* op = (uint32_t*)out;
    op[2 * i]     = pack_f16x2(v.x, v.y);
    op[2 * i + 1] = pack_f16x2(v.z, v.w);
}

__global__ void convT_f16_kernel(const float* __restrict__ in,
                                 __half* __restrict__ outT, int K, int N) {
    __shared__ float t[32][33];
    int nx = blockIdx.x * 32, ky = blockIdx.y * 32;
    int tx = threadIdx.x, ty = threadIdx.y;   // block (32, 8)
#pragma unroll
    for (int i = 0; i < 4; i++)
        t[ty + i * 8][tx] = in[(size_t)(ky + ty + i * 8) * N + nx + tx];
    __syncthreads();
#pragma unroll
    for (int i = 0; i < 4; i++) {
        float v = t[tx][ty + i * 8];
        int n = nx + ty + i * 8, k = ky + tx;
        outT[(size_t)n * K + k] = __float2half_rn(v);
    }
}

// ---------------------------------------------------------------------------
// HMMA fp16 GEMM (single-term): C = A @ B^T + bias (B as [N,K]).
// mode 0: fp32 out -> Cf.  mode 1: fp16 out -> Ch, cols<qcols scaled QSCALE.
// ---------------------------------------------------------------------------
#define ROWB      80u
#define OP_BYTES  (128u * ROWB)       // 10240
#define STG_BYTES (2u * OP_BYTES)     // 20480 (A + B)
#define GEMM_SMEM (2u * STG_BYTES)    // 40960

__device__ __forceinline__ uint32_t a_frag_addr(uint32_t base, int mr, int ks, int lane) {
    int row = mr + (lane & 7) + ((lane >> 3) & 1) * 8;
    int kb  = ks * 32 + (lane >> 4) * 16;
    return base + row * ROWB + kb;
}
__device__ __forceinline__ uint32_t b_frag_addr(uint32_t base, int nr, int ks, int lane) {
    int row = nr + (lane & 7) + (lane >> 4) * 8;
    int kb  = ks * 32 + ((lane >> 3) & 1) * 16;
    return base + row * ROWB + kb;
}

__global__ __launch_bounds__(256, 2)
void gemm_hmma_f16_kernel(const __half* __restrict__ A, const __half* __restrict__ B,
                          const float* __restrict__ bias,
                          float* __restrict__ Cf, __half* __restrict__ Ch,
                          int M, int N, int K, int mode, int qcols) {
    extern __shared__ char smem[];
    const uint32_t sb = smem_u32(smem);
    const int tid = threadIdx.x;
    const int lane = tid & 31;
    const int wid = tid >> 5;
    const int wm = (wid & 1) * 64;
    const int wn = (wid >> 1) * 32;
    const int row0 = blockIdx.y * 128, col0 = blockIdx.x * 128;

    const __half* srcs[2] = { A + (size_t)row0 * K, B + (size_t)col0 * K };

    const int pos0 = tid, pos1 = tid + 256;
    const int r0l = pos0 >> 2, c0l = pos0 & 3;
    const int r1l = pos1 >> 2, c1l = pos1 & 3;

    float acc[4][4][4];
#pragma unroll
    for (int mt = 0; mt < 4; mt++)
#pragma unroll
        for (int nt = 0; nt < 4; nt++)
#pragma unroll
            for (int e = 0; e < 4; e++) acc[mt][nt][e] = 0.f;

    const int nchunk = K / 32;
    {
        uint32_t st = sb;
#pragma unroll
        for (int op = 0; op < 2; op++) {
            const __half* s = srcs[op];
            CP_ASYNC16(st + op * OP_BYTES + r0l * ROWB + c0l * 16, s + (size_t)r0l * K + c0l * 8);
            CP_ASYNC16(st + op * OP_BYTES + r1l * ROWB + c1l * 16, s + (size_t)r1l * K + c1l * 8);
        }
        CP_COMMIT();
    }

    for (int ch = 0; ch < nchunk; ch++) {
        if (ch + 1 < nchunk) {
            uint32_t st = sb + ((ch + 1) & 1) * STG_BYTES;
            const int k0 = (ch + 1) * 32;
#pragma unroll
            for (int op = 0; op < 2; op++) {
                const __half* s = srcs[op];
                CP_ASYNC16(st + op * OP_BYTES + r0l * ROWB + c0l * 16, s + (size_t)r0l * K + k0 + c0l * 8);
                CP_ASYNC16(st + op * OP_BYTES + r1l * ROWB + c1l * 16, s + (size_t)r1l * K + k0 + c1l * 8);
            }
            CP_COMMIT();
            CP_WAIT(1);
        } else {
            CP_WAIT(0);
        }
        __syncthreads();

        const uint32_t st = sb + (ch & 1) * STG_BYTES;
        const uint32_t sA = st, sB = st + OP_BYTES;

#pragma unroll
        for (int ks = 0; ks < 2; ks++) {
            uint32_t ah[4][4], bh[2][4];
#pragma unroll
            for (int mt = 0; mt < 4; mt++)
                ldsm_x4(ah[mt], a_frag_addr(sA, wm + 16 * mt, ks, lane));
#pragma unroll
            for (int g = 0; g < 2; g++)
                ldsm_x4(bh[g], b_frag_addr(sB, wn + 16 * g, ks, lane));
#pragma unroll
            for (int mt = 0; mt < 4; mt++)
#pragma unroll
                for (int g = 0; g < 2; g++) {
                    mma_f16(acc[mt][2 * g],     ah[mt], &bh[g][0]);
                    mma_f16(acc[mt][2 * g + 1], ah[mt], &bh[g][2]);
                }
        }
        __syncthreads();
    }

#pragma unroll
    for (int mt = 0; mt < 4; mt++) {
        int r = row0 + wm + 16 * mt + (lane >> 2);
#pragma unroll
        for (int nt = 0; nt < 4; nt++) {
            int c = col0 + wn + 8 * nt + (lane & 3) * 2;
            float bx = __ldg(&bias[c]), by = __ldg(&bias[c + 1]);
            float x0 = acc[mt][nt][0] + bx, x1 = acc[mt][nt][1] + by;
            float x2 = acc[mt][nt][2] + bx, x3 = acc[mt][nt][3] + by;
            if (mode == 0) {
                float2 v0 = { x0, x1 }, v1 = { x2, x3 };
                *(float2*)&Cf[(size_t)r * N + c]       = v0;
                *(float2*)&Cf[(size_t)(r + 8) * N + c] = v1;
            } else {
                float sc = (c < qcols) ? QSCALE : 1.f;
                *(uint32_t*)&Ch[(size_t)r * N + c]       = pack_f16x2(x0 * sc, x1 * sc);
                *(uint32_t*)&Ch[(size_t)(r + 8) * N + c] = pack_f16x2(x2 * sc, x3 * sc);
            }
        }
    }
}

// ---------------------------------------------------------------------------
// HMMA fp16 flash attention (causal, single-term). Block = 128 queries of one
// (b,h). Heavy-first q ordering. Softmax in log2 domain (ex2.approx).
// ---------------------------------------------------------------------------
#define ROWA       144u               // 64 fp16 = 128B data + 16B pad
#define AQ_BYTES   (128u * ROWA)      // 18432
#define AKV_BYTES  (64u * ROWA)       // 9216
#define KV_STAGE   (2u * AKV_BYTES)   // 18432 (K + V)
#define ATT_SMEM   (AQ_BYTES + 2u * KV_STAGE)   // 55296

__device__ __forceinline__ uint32_t afragA(uint32_t base, int mr, int ks, int lane) {
    int row = mr + (lane & 7) + ((lane >> 3) & 1) * 8;
    int kb  = ks * 32 + (lane >> 4) * 16;
    return base + row * ROWA + kb;
}
__device__ __forceinline__ uint32_t bfragA(uint32_t base, int nr, int ks, int lane) {
    int row = nr + (lane & 7) + (lane >> 4) * 8;
    int kb  = ks * 32 + ((lane >> 3) & 1) * 16;
    return base + row * ROWA + kb;
}
// V (trans) fragment: p covers d-cols 16p..16p+15.
__device__ __forceinline__ uint32_t vfragA(uint32_t base, int ks, int p, int lane) {
    int row = ks * 16 + (lane & 15);
    int col = p * 32 + ((lane >> 4) & 1) * 16;
    return base + row * ROWA + col;
}

__global__ __launch_bounds__(256, 2)
void flash_attn_f16_kernel(const __half* __restrict__ qkv,
                           __half* __restrict__ o16) {
    extern __shared__ char smem[];
    const uint32_t sb = smem_u32(smem);
    const int tid = threadIdx.x, lane = tid & 31, wid = tid >> 5;
    const int bh = blockIdx.y, b = bh >> 4, h = bh & 15;
    const int q0 = (gridDim.x - 1 - blockIdx.x) * 128;   // heavy-first
    const int wrow = wid * 16;

    const size_t rowbase = (size_t)b * T_SEQ;
    const int qc = h * DH, kc = CDIM + h * DH, vc = 2 * CDIM + h * DH;
    const uint32_t kvb = sb + AQ_BYTES;

    // Q load: 128 rows x 8 chunks
#pragma unroll
    for (int t = 0; t < 4; t++) {
        int ci = tid + t * 256;
        int r = ci >> 3, c = ci & 7;
        CP_ASYNC16(sb + r * ROWA + c * 16, qkv + (rowbase + q0 + r) * C3 + qc + c * 8);
    }
    // KV tile 0 into stage 0 (K: 512 chunks, V: 512 chunks)
    {
        const uint32_t base = kvb;
#pragma unroll
        for (int t = 0; t < 2; t++) {
            int ci = tid + t * 256;
            int r = ci >> 3, c = ci & 7;
            const size_t grow = (rowbase + r) * C3;
            CP_ASYNC16(base + r * ROWA + c * 16,              qkv + grow + kc + c * 8);
            CP_ASYNC16(base + AKV_BYTES + r * ROWA + c * 16,  qkv + grow + vc + c * 8);
        }
        CP_COMMIT();
    }

    float m0 = -INFINITY, m1 = -INFINITY, l0 = 0.f, l1 = 0.f;
    float o[8][4];
#pragma unroll
    for (int n = 0; n < 8; n++)
#pragma unroll
        for (int e = 0; e < 4; e++) o[n][e] = 0.f;

    const int ntiles = q0 / 64 + 2;
    for (int kt = 0; kt < ntiles; kt++) {
        __syncthreads();   // all warps done reading the stage we're about to overwrite
        if (kt + 1 < ntiles) {
            const uint32_t base = kvb + ((kt + 1) & 1) * KV_STAGE;
            const int k0n = (kt + 1) * 64;
#pragma unroll
            for (int t = 0; t < 2; t++) {
                int ci = tid + t * 256;
                int r = ci >> 3, c = ci & 7;
                const size_t grow = (rowbase + k0n + r) * C3;
                CP_ASYNC16(base + r * ROWA + c * 16,             qkv + grow + kc + c * 8);
                CP_ASYNC16(base + AKV_BYTES + r * ROWA + c * 16, qkv + grow + vc + c * 8);
            }
            CP_COMMIT();
            CP_WAIT(1);
        } else {
            CP_WAIT(0);
        }
        __syncthreads();

        const int k0 = kt * 64;
        const uint32_t stg = kvb + (kt & 1) * KV_STAGE;
        const uint32_t sK = stg, sV = stg + AKV_BYTES;

        // ---- S = Q K^T (log2 domain) ----
        float s[8][4];
#pragma unroll
        for (int n = 0; n < 8; n++)
#pragma unroll
            for (int e = 0; e < 4; e++) s[n][e] = 0.f;

#pragma unroll
        for (int ks = 0; ks < 4; ks++) {
            uint32_t qh[4];
            ldsm_x4(qh, afragA(sb, wrow, ks, lane));
#pragma unroll
            for (int g = 0; g < 4; g++) {
                uint32_t kh[4];
                ldsm_x4(kh, bfragA(sK, g * 16, ks, lane));
                mma_f16(s[2 * g],     qh, &kh[0]);
                mma_f16(s[2 * g + 1], qh, &kh[2]);
            }
        }

        // ---- causal mask ----
        if (k0 + 63 > q0 + wrow) {
            const int r0g = q0 + wrow + (lane >> 2);
#pragma unroll
            for (int n = 0; n < 8; n++) {
                int cg = k0 + n * 8 + (lane & 3) * 2;
#pragma unroll
                for (int e = 0; e < 4; e++) {
                    int rg = r0g + ((e >> 1) << 3);
                    int cc = cg + (e & 1);
                    if (cc > rg) s[n][e] = -INFINITY;
                }
            }
        }

        // ---- online softmax (log2 domain, ex2) ----
        float mx0 = m0, mx1 = m1;
#pragma unroll
        for (int n = 0; n < 8; n++) {
            mx0 = fmaxf(mx0, fmaxf(s[n][0], s[n][1]));
            mx1 = fmaxf(mx1, fmaxf(s[n][2], s[n][3]));
        }
        mx0 = fmaxf(mx0, __shfl_xor_sync(0xffffffffu, mx0, 1));
        mx0 = fmaxf(mx0, __shfl_xor_sync(0xffffffffu, mx0, 2));
        mx1 = fmaxf(mx1, __shfl_xor_sync(0xffffffffu, mx1, 1));
        mx1 = fmaxf(mx1, __shfl_xor_sync(0xffffffffu, mx1, 2));
        float a0 = ex2f(m0 - mx0), a1 = ex2f(m1 - mx1);
        m0 = mx0; m1 = mx1;

        float sum0 = 0.f, sum1 = 0.f;
#pragma unroll
        for (int n = 0; n < 8; n++) {
            s[n][0] = ex2f(s[n][0] - mx0); sum0 += s[n][0];
            s[n][1] = ex2f(s[n][1] - mx0); sum0 += s[n][1];
            s[n][2] = ex2f(s[n][2] - mx1); sum1 += s[n][2];
            s[n][3] = ex2f(s[n][3] - mx1); sum1 += s[n][3];
        }
        sum0 += __shfl_xor_sync(0xffffffffu, sum0, 1);
        sum0 += __shfl_xor_sync(0xffffffffu, sum0, 2);
        sum1 += __shfl_xor_sync(0xffffffffu, sum1, 1);
        sum1 += __shfl_xor_sync(0xffffffffu, sum1, 2);
        l0 = l0 * a0 + sum0;
        l1 = l1 * a1 + sum1;

#pragma unroll
        for (int n = 0; n < 8; n++) {
            o[n][0] *= a0; o[n][1] *= a0;
            o[n][2] *= a1; o[n][3] *= a1;
        }

        // ---- O += P V ----
#pragma unroll
        for (int ks = 0; ks < 4; ks++) {
            uint32_t ph[4];
            ph[0] = pack_f16x2(s[2 * ks][0],     s[2 * ks][1]);
            ph[1] = pack_f16x2(s[2 * ks][2],     s[2 * ks][3]);
            ph[2] = pack_f16x2(s[2 * ks + 1][0], s[2 * ks + 1][1]);
            ph[3] = pack_f16x2(s[2 * ks + 1][2], s[2 * ks + 1][3]);
#pragma unroll
            for (int p = 0; p < 4; p++) {
                uint32_t vh[4];
                ldsm_x4_t(vh, vfragA(sV, ks, p, lane));
                mma_f16(o[2 * p],     ph, &vh[0]);
                mma_f16(o[2 * p + 1], ph, &vh[2]);
            }
        }
    }

    // ---- epilogue: normalize + fp16 store ----
    const float inv0 = 1.f / l0, inv1 = 1.f / l1;
    const int r0g = q0 + wrow + (lane >> 2);
    const size_t ro0 = (rowbase + r0g) * CDIM + h * DH;
    const size_t ro1 = (rowbase + r0g + 8) * CDIM + h * DH;
#pragma unroll
    for (int n = 0; n < 8; n++) {
        int c = n * 8 + (lane & 3) * 2;
        *(uint32_t*)&o16[ro0 + c] = pack_f16x2(o[n][0] * inv0, o[n][1] * inv0);
        *(uint32_t*)&o16[ro1 + c] = pack_f16x2(o[n][2] * inv1, o[n][3] * inv1);
    }
}

// ---------------------------------------------------------------------------
// Launch
// ---------------------------------------------------------------------------
extern "C" void kernel_launch(void* const* d_in, const int* in_sizes, int n_in,
                              void* d_out, int out_size) {
    const float* x      = (const float*)d_in[0];
    const float* w_qkv  = (const float*)d_in[1];
    const float* b_qkv  = (const float*)d_in[2];
    const float* w_proj = (const float*)d_in[3];
    const float* b_proj = (const float*)d_in[4];
    float* out = (float*)d_out;

    __half *qkv16, *x16, *wqT, *wpT, *attn16;
    cudaGetSymbolAddress((void**)&qkv16, g_qkv16);
    cudaGetSymbolAddress((void**)&x16, g_x16);
    cudaGetSymbolAddress((void**)&wqT, g_wqkvT);
    cudaGetSymbolAddress((void**)&wpT, g_wprojT);
    cudaGetSymbolAddress((void**)&attn16, g_attn16);

    cudaFuncSetAttribute(gemm_hmma_f16_kernel,
                         cudaFuncAttributeMaxDynamicSharedMemorySize, (int)GEMM_SMEM);
    cudaFuncSetAttribute(flash_attn_f16_kernel,
                         cudaFuncAttributeMaxDynamicSharedMemorySize, (int)ATT_SMEM);

    // 0) operand conversion
    {
        int n4 = MROWS * CDIM / 4;
        conv_f16_kernel<<<(n4 + 255) / 256, 256>>>(x, x16, n4);
        dim3 blk(32, 8);
        convT_f16_kernel<<<dim3(C3 / 32, CDIM / 32), blk>>>(w_qkv, wqT, CDIM, C3);
        convT_f16_kernel<<<dim3(CDIM / 32, CDIM / 32), blk>>>(w_proj, wpT, CDIM, CDIM);
    }

    // 1) QKV projection -> fp16 (Q pre-scaled by 0.125*log2e)
    gemm_hmma_f16_kernel<<<dim3(C3 / 128, MROWS / 128), 256, GEMM_SMEM>>>(
        x16, wqT, b_qkv, nullptr, qkv16, MROWS, C3, CDIM, 1, CDIM);

    // 2) fp16 flash attention -> fp16
    flash_attn_f16_kernel<<<dim3(T_SEQ / 128, BATCH * NH), 256, ATT_SMEM>>>(
        qkv16, attn16);

    // 3) Output projection -> fp32 d_out
    gemm_hmma_f16_kernel<<<dim3(CDIM / 128, MROWS / 128), 256, GEMM_SMEM>>>(
        attn16, wpT, b_proj, out, nullptr, MROWS, CDIM, CDIM, 0, 0);
}

// round 16
// speedup vs baseline: 2.4401x; 1.1046x over previous
#include <cuda_runtime.h>
#include <cuda_fp16.h>
#include <math.h>
#include <stdint.h>

// Problem constants
#define BATCH   2
#define T_SEQ   2048
#define CDIM    1024
#define NH      16
#define DH      64
#define C3      (3 * CDIM)
#define MROWS   (BATCH * T_SEQ)   // 4096

// Q pre-scale: (1/sqrt(64)) * log2(e)  -> softmax uses ex2 directly
#define QSCALE  0.18033688011112042f

// ---------------------------------------------------------------------------
// Scratch (device globals — no cudaMalloc allowed)
// ---------------------------------------------------------------------------
__device__ __half g_qkv16 [(size_t)MROWS * C3];    // [B*T, 3C]
__device__ __half g_x16   [(size_t)MROWS * CDIM];
__device__ __half g_wqkvT [(size_t)C3 * CDIM];     // [3072,1024] ([N,K])
__device__ __half g_wprojT[(size_t)CDIM * CDIM];
__device__ __half g_attn16[(size_t)MROWS * CDIM];

// ---------------------------------------------------------------------------
// PTX helpers
// ---------------------------------------------------------------------------
__device__ __forceinline__ uint32_t smem_u32(const void* p) {
    uint32_t a;
    asm("{ .reg .u64 t; cvta.to.shared.u64 t, %1; cvt.u32.u64 %0, t; }" : "=r"(a) : "l"(p));
    return a;
}

#define CP_ASYNC16(dst, src)   asm volatile("cp.async.cg.shared.global [%0], [%1], 16;" :: "r"(dst), "l"(src) : "memory")
#define CP_COMMIT()            asm volatile("cp.async.commit_group;" ::: "memory")
#define CP_WAIT(n)             asm volatile("cp.async.wait_group %0;" :: "n"(n) : "memory")

__device__ __forceinline__ void ldsm_x4(uint32_t* r, uint32_t addr) {
    asm volatile("ldmatrix.sync.aligned.m8n8.x4.shared.b16 {%0,%1,%2,%3}, [%4];"
        : "=r"(r[0]), "=r"(r[1]), "=r"(r[2]), "=r"(r[3]) : "r"(addr));
}
__device__ __forceinline__ void ldsm_x4_t(uint32_t* r, uint32_t addr) {
    asm volatile("ldmatrix.sync.aligned.m8n8.x4.trans.shared.b16 {%0,%1,%2,%3}, [%4];"
        : "=r"(r[0]), "=r"(r[1]), "=r"(r[2]), "=r"(r[3]) : "r"(addr));
}
__device__ __forceinline__ void mma_f16(float* d, const uint32_t* a, const uint32_t* b) {
    asm volatile(
        "mma.sync.aligned.m16n8k16.row.col.f32.f16.f16.f32 "
        "{%0,%1,%2,%3}, {%4,%5,%6,%7}, {%8,%9}, {%0,%1,%2,%3};"
        : "+f"(d[0]), "+f"(d[1]), "+f"(d[2]), "+f"(d[3])
        : "r"(a[0]), "r"(a[1]), "r"(a[2]), "r"(a[3]), "r"(b[0]), "r"(b[1]));
}

__device__ __forceinline__ float ex2f(float x) {
    float r;
    asm("ex2.approx.f32 %0, %1;" : "=f"(r) : "f"(x));
    return r;
}
// pack two fp32 -> fp16x2, low half = a, high half = b (RN)
__device__ __forceinline__ uint32_t pack_f16x2(float a, float b) {
    uint32_t r;
    asm("cvt.rn.f16x2.f32 %0, %1, %2;" : "=r"(r) : "f"(b), "f"(a));
    return r;
}

// ---------------------------------------------------------------------------
// Conversion kernels (fp32 -> fp16)
// ---------------------------------------------------------------------------
__global__ void conv_f16_kernel(const float* __restrict__ in,
                                __half* __restrict__ out, int n4) {
    int i = blockIdx.x * blockDim.x + threadIdx.x;
    if (i >= n4) return;
    float4 v = ((const float4*)in)[i];
    uint32_t* op = (uint32_t*)out;
    op[2 * i]     = pack_f16x2(v.x, v.y);
    op[2 * i + 1] = pack_f16x2(v.z, v.w);
}

__global__ void convT_f16_kernel(const float* __restrict__ in,
                                 __half* __restrict__ outT, int K, int N) {
    __shared__ float t[32][33];
    int nx = blockIdx.x * 32, ky = blockIdx.y * 32;
    int tx = threadIdx.x, ty = threadIdx.y;   // block (32, 8)
#pragma unroll
    for (int i = 0; i < 4; i++)
        t[ty + i * 8][tx] = in[(size_t)(ky + ty + i * 8) * N + nx + tx];
    __syncthreads();
#pragma unroll
    for (int i = 0; i < 4; i++) {
        float v = t[tx][ty + i * 8];
        int n = nx + ty + i * 8, k = ky + tx;
        outT[(size_t)n * K + k] = __float2half_rn(v);
    }
}

// ---------------------------------------------------------------------------
// HMMA fp16 GEMM: C = A @ B^T + bias (B as [N,K]).
// 4-stage cp.async ring, ONE __syncthreads per chunk.
// mode 0: fp32 out -> Cf.  mode 1: fp16 out -> Ch, cols<qcols scaled QSCALE.
// ---------------------------------------------------------------------------
#define ROWB      80u
#define OP_BYTES  (128u * ROWB)       // 10240
#define STG_BYTES (2u * OP_BYTES)     // 20480 (A + B)
#define GEMM_STAGES 4
#define GEMM_SMEM (4u * STG_BYTES)    // 81920 (2 CTAs -> 160KB)

__device__ __forceinline__ uint32_t a_frag_addr(uint32_t base, int mr, int ks, int lane) {
    int row = mr + (lane & 7) + ((lane >> 3) & 1) * 8;
    int kb  = ks * 32 + (lane >> 4) * 16;
    return base + row * ROWB + kb;
}
__device__ __forceinline__ uint32_t b_frag_addr(uint32_t base, int nr, int ks, int lane) {
    int row = nr + (lane & 7) + (lane >> 4) * 8;
    int kb  = ks * 32 + ((lane >> 3) & 1) * 16;
    return base + row * ROWB + kb;
}

__global__ __launch_bounds__(256, 2)
void gemm_hmma_f16_kernel(const __half* __restrict__ A, const __half* __restrict__ B,
                          const float* __restrict__ bias,
                          float* __restrict__ Cf, __half* __restrict__ Ch,
                          int M, int N, int K, int mode, int qcols) {
    extern __shared__ char smem[];
    const uint32_t sb = smem_u32(smem);
    const int tid = threadIdx.x;
    const int lane = tid & 31;
    const int wid = tid >> 5;
    const int wm = (wid & 1) * 64;
    const int wn = (wid >> 1) * 32;
    const int row0 = blockIdx.y * 128, col0 = blockIdx.x * 128;

    const __half* srcs[2] = { A + (size_t)row0 * K, B + (size_t)col0 * K };

    const int pos0 = tid, pos1 = tid + 256;
    const int r0l = pos0 >> 2, c0l = pos0 & 3;
    const int r1l = pos1 >> 2, c1l = pos1 & 3;

    float acc[4][4][4];
#pragma unroll
    for (int mt = 0; mt < 4; mt++)
#pragma unroll
        for (int nt = 0; nt < 4; nt++)
#pragma unroll
            for (int e = 0; e < 4; e++) acc[mt][nt][e] = 0.f;

    const int nchunk = K / 32;

    // Prologue: prefetch chunks 0..2, one commit group each.
#pragma unroll
    for (int pf = 0; pf < GEMM_STAGES - 1; pf++) {
        uint32_t st = sb + pf * STG_BYTES;
        const int k0 = pf * 32;
#pragma unroll
        for (int op = 0; op < 2; op++) {
            const __half* s = srcs[op];
            CP_ASYNC16(st + op * OP_BYTES + r0l * ROWB + c0l * 16, s + (size_t)r0l * K + k0 + c0l * 8);
            CP_ASYNC16(st + op * OP_BYTES + r1l * ROWB + c1l * 16, s + (size_t)r1l * K + k0 + c1l * 8);
        }
        CP_COMMIT();
    }

    for (int ch = 0; ch < nchunk; ch++) {
        CP_WAIT(GEMM_STAGES - 2);    // chunk ch landed
        __syncthreads();             // everyone done reading stage (ch-1)&3 too

        const uint32_t st = sb + (ch & (GEMM_STAGES - 1)) * STG_BYTES;
        const uint32_t sA = st, sB = st + OP_BYTES;

#pragma unroll
        for (int ks = 0; ks < 2; ks++) {
            uint32_t ah[4][4], bh[2][4];
#pragma unroll
            for (int mt = 0; mt < 4; mt++)
                ldsm_x4(ah[mt], a_frag_addr(sA, wm + 16 * mt, ks, lane));
#pragma unroll
            for (int g = 0; g < 2; g++)
                ldsm_x4(bh[g], b_frag_addr(sB, wn + 16 * g, ks, lane));
#pragma unroll
            for (int mt = 0; mt < 4; mt++)
#pragma unroll
                for (int g = 0; g < 2; g++) {
                    mma_f16(acc[mt][2 * g],     ah[mt], &bh[g][0]);
                    mma_f16(acc[mt][2 * g + 1], ah[mt], &bh[g][2]);
                }
        }

        // Prefetch chunk ch+3 into stage (ch+3)&3 == (ch-1)&3 (safe: barrier above)
        if (ch + GEMM_STAGES - 1 < nchunk) {
            uint32_t stn = sb + ((ch + GEMM_STAGES - 1) & (GEMM_STAGES - 1)) * STG_BYTES;
            const int k0 = (ch + GEMM_STAGES - 1) * 32;
#pragma unroll
            for (int op = 0; op < 2; op++) {
                const __half* s = srcs[op];
                CP_ASYNC16(stn + op * OP_BYTES + r0l * ROWB + c0l * 16, s + (size_t)r0l * K + k0 + c0l * 8);
                CP_ASYNC16(stn + op * OP_BYTES + r1l * ROWB + c1l * 16, s + (size_t)r1l * K + k0 + c1l * 8);
            }
        }
        CP_COMMIT();   // unconditional: keeps group accounting exact at the tail
    }

#pragma unroll
    for (int mt = 0; mt < 4; mt++) {
        int r = row0 + wm + 16 * mt + (lane >> 2);
#pragma unroll
        for (int nt = 0; nt < 4; nt++) {
            int c = col0 + wn + 8 * nt + (lane & 3) * 2;
            float bx = __ldg(&bias[c]), by = __ldg(&bias[c + 1]);
            float x0 = acc[mt][nt][0] + bx, x1 = acc[mt][nt][1] + by;
            float x2 = acc[mt][nt][2] + bx, x3 = acc[mt][nt][3] + by;
            if (mode == 0) {
                float2 v0 = { x0, x1 }, v1 = { x2, x3 };
                *(float2*)&Cf[(size_t)r * N + c]       = v0;
                *(float2*)&Cf[(size_t)(r + 8) * N + c] = v1;
            } else {
                float sc = (c < qcols) ? QSCALE : 1.f;
                *(uint32_t*)&Ch[(size_t)r * N + c]       = pack_f16x2(x0 * sc, x1 * sc);
                *(uint32_t*)&Ch[(size_t)(r + 8) * N + c] = pack_f16x2(x2 * sc, x3 * sc);
            }
        }
    }
}

// ---------------------------------------------------------------------------
// HMMA fp16 flash attention (causal). Block = 128 queries of one (b,h).
// 3-stage KV ring, ONE __syncthreads per tile. Heavy-first q ordering.
// Softmax in log2 domain (ex2.approx).
// ---------------------------------------------------------------------------
#define ROWA       144u               // 64 fp16 = 128B data + 16B pad
#define AQ_BYTES   (128u * ROWA)      // 18432
#define AKV_BYTES  (64u * ROWA)       // 9216
#define KV_STAGE   (2u * AKV_BYTES)   // 18432 (K + V)
#define KV_STAGES  3
#define ATT_SMEM   (AQ_BYTES + 3u * KV_STAGE)   // 73728 (2 CTAs -> 147456)

__device__ __forceinline__ uint32_t afragA(uint32_t base, int mr, int ks, int lane) {
    int row = mr + (lane & 7) + ((lane >> 3) & 1) * 8;
    int kb  = ks * 32 + (lane >> 4) * 16;
    return base + row * ROWA + kb;
}
__device__ __forceinline__ uint32_t bfragA(uint32_t base, int nr, int ks, int lane) {
    int row = nr + (lane & 7) + (lane >> 4) * 8;
    int kb  = ks * 32 + ((lane >> 3) & 1) * 16;
    return base + row * ROWA + kb;
}
// V (trans) fragment: p covers d-cols 16p..16p+15.
__device__ __forceinline__ uint32_t vfragA(uint32_t base, int ks, int p, int lane) {
    int row = ks * 16 + (lane & 15);
    int col = p * 32 + ((lane >> 4) & 1) * 16;
    return base + row * ROWA + col;
}

__global__ __launch_bounds__(256, 2)
void flash_attn_f16_kernel(const __half* __restrict__ qkv,
                           __half* __restrict__ o16) {
    extern __shared__ char smem[];
    const uint32_t sb = smem_u32(smem);
    const int tid = threadIdx.x, lane = tid & 31, wid = tid >> 5;
    const int bh = blockIdx.y, b = bh >> 4, h = bh & 15;
    const int q0 = (gridDim.x - 1 - blockIdx.x) * 128;   // heavy-first
    const int wrow = wid * 16;

    const size_t rowbase = (size_t)b * T_SEQ;
    const int qc = h * DH, kc = CDIM + h * DH, vc = 2 * CDIM + h * DH;
    const uint32_t kvb = sb + AQ_BYTES;

    const int ntiles = q0 / 64 + 2;

    // Prologue group 0: Q + KV tile 0.  Group 1: KV tile 1.
#pragma unroll
    for (int t = 0; t < 4; t++) {
        int ci = tid + t * 256;
        int r = ci >> 3, c = ci & 7;
        CP_ASYNC16(sb + r * ROWA + c * 16, qkv + (rowbase + q0 + r) * C3 + qc + c * 8);
    }
    {
#pragma unroll
        for (int t = 0; t < 2; t++) {
            int ci = tid + t * 256;
            int r = ci >> 3, c = ci & 7;
            const size_t grow = (rowbase + r) * C3;
            CP_ASYNC16(kvb + r * ROWA + c * 16,             qkv + grow + kc + c * 8);
            CP_ASYNC16(kvb + AKV_BYTES + r * ROWA + c * 16, qkv + grow + vc + c * 8);
        }
        CP_COMMIT();
    }
    {
        const uint32_t base = kvb + (1 % KV_STAGES) * KV_STAGE;
        if (1 < ntiles) {
#pragma unroll
            for (int t = 0; t < 2; t++) {
                int ci = tid + t * 256;
                int r = ci >> 3, c = ci & 7;
                const size_t grow = (rowbase + 64 + r) * C3;
                CP_ASYNC16(base + r * ROWA + c * 16,             qkv + grow + kc + c * 8);
                CP_ASYNC16(base + AKV_BYTES + r * ROWA + c * 16, qkv + grow + vc + c * 8);
            }
        }
        CP_COMMIT();
    }

    float m0 = -INFINITY, m1 = -INFINITY, l0 = 0.f, l1 = 0.f;
    float o[8][4];
#pragma unroll
    for (int n = 0; n < 8; n++)
#pragma unroll
        for (int e = 0; e < 4; e++) o[n][e] = 0.f;

    int stg_idx = 0;  // kt % 3
    for (int kt = 0; kt < ntiles; kt++) {
        CP_WAIT(1);          // tile kt (and Q, at kt=0) landed
        __syncthreads();     // all warps done reading stage (kt-1)%3

        const int k0 = kt * 64;
        const uint32_t stg = kvb + stg_idx * KV_STAGE;
        const uint32_t sK = stg, sV = stg + AKV_BYTES;

        // ---- S = Q K^T (log2 domain) ----
        float s[8][4];
#pragma unroll
        for (int n = 0; n < 8; n++)
#pragma unroll
            for (int e = 0; e < 4; e++) s[n][e] = 0.f;

#pragma unroll
        for (int ks = 0; ks < 4; ks++) {
            uint32_t qh[4];
            ldsm_x4(qh, afragA(sb, wrow, ks, lane));
#pragma unroll
            for (int g = 0; g < 4; g++) {
                uint32_t kh[4];
                ldsm_x4(kh, bfragA(sK, g * 16, ks, lane));
                mma_f16(s[2 * g],     qh, &kh[0]);
                mma_f16(s[2 * g + 1], qh, &kh[2]);
            }
        }

        // Prefetch tile kt+2 into stage (kt+2)%3 == (kt-1)%3 (safe: barrier above)
        {
            int ktn = kt + KV_STAGES - 1;
            if (ktn < ntiles) {
                const uint32_t base = kvb + ((stg_idx + KV_STAGES - 1) % KV_STAGES) * KV_STAGE;
                const int k0n = ktn * 64;
#pragma unroll
                for (int t = 0; t < 2; t++) {
                    int ci = tid + t * 256;
                    int r = ci >> 3, c = ci & 7;
                    const size_t grow = (rowbase + k0n + r) * C3;
                    CP_ASYNC16(base + r * ROWA + c * 16,             qkv + grow + kc + c * 8);
                    CP_ASYNC16(base + AKV_BYTES + r * ROWA + c * 16, qkv + grow + vc + c * 8);
                }
            }
            CP_COMMIT();
        }

        // ---- causal mask ----
        if (k0 + 63 > q0 + wrow) {
            const int r0g = q0 + wrow + (lane >> 2);
#pragma unroll
            for (int n = 0; n < 8; n++) {
                int cg = k0 + n * 8 + (lane & 3) * 2;
#pragma unroll
                for (int e = 0; e < 4; e++) {
                    int rg = r0g + ((e >> 1) << 3);
                    int cc = cg + (e & 1);
                    if (cc > rg) s[n][e] = -INFINITY;
                }
            }
        }

        // ---- online softmax (log2 domain, ex2) ----
        float mx0 = m0, mx1 = m1;
#pragma unroll
        for (int n = 0; n < 8; n++) {
            mx0 = fmaxf(mx0, fmaxf(s[n][0], s[n][1]));
            mx1 = fmaxf(mx1, fmaxf(s[n][2], s[n][3]));
        }
        mx0 = fmaxf(mx0, __shfl_xor_sync(0xffffffffu, mx0, 1));
        mx0 = fmaxf(mx0, __shfl_xor_sync(0xffffffffu, mx0, 2));
        mx1 = fmaxf(mx1, __shfl_xor_sync(0xffffffffu, mx1, 1));
        mx1 = fmaxf(mx1, __shfl_xor_sync(0xffffffffu, mx1, 2));
        float a0 = ex2f(m0 - mx0), a1 = ex2f(m1 - mx1);
        m0 = mx0; m1 = mx1;

        float sum0 = 0.f, sum1 = 0.f;
#pragma unroll
        for (int n = 0; n < 8; n++) {
            s[n][0] = ex2f(s[n][0] - mx0); sum0 += s[n][0];
            s[n][1] = ex2f(s[n][1] - mx0); sum0 += s[n][1];
            s[n][2] = ex2f(s[n][2] - mx1); sum1 += s[n][2];
            s[n][3] = ex2f(s[n][3] - mx1); sum1 += s[n][3];
        }
        sum0 += __shfl_xor_sync(0xffffffffu, sum0, 1);
        sum0 += __shfl_xor_sync(0xffffffffu, sum0, 2);
        sum1 += __shfl_xor_sync(0xffffffffu, sum1, 1);
        sum1 += __shfl_xor_sync(0xffffffffu, sum1, 2);
        l0 = l0 * a0 + sum0;
        l1 = l1 * a1 + sum1;

#pragma unroll
        for (int n = 0; n < 8; n++) {
            o[n][0] *= a0; o[n][1] *= a0;
            o[n][2] *= a1; o[n][3] *= a1;
        }

        // ---- O += P V ----
#pragma unroll
        for (int ks = 0; ks < 4; ks++) {
            uint32_t ph[4];
            ph[0] = pack_f16x2(s[2 * ks][0],     s[2 * ks][1]);
            ph[1] = pack_f16x2(s[2 * ks][2],     s[2 * ks][3]);
            ph[2] = pack_f16x2(s[2 * ks + 1][0], s[2 * ks + 1][1]);
            ph[3] = pack_f16x2(s[2 * ks + 1][2], s[2 * ks + 1][3]);
#pragma unroll
            for (int p = 0; p < 4; p++) {
                uint32_t vh[4];
                ldsm_x4_t(vh, vfragA(sV, ks, p, lane));
                mma_f16(o[2 * p],     ph, &vh[0]);
                mma_f16(o[2 * p + 1], ph, &vh[2]);
            }
        }

        stg_idx++;
        if (stg_idx == KV_STAGES) stg_idx = 0;
    }

    // ---- epilogue: normalize + fp16 store ----
    const float inv0 = 1.f / l0, inv1 = 1.f / l1;
    const int r0g = q0 + wrow + (lane >> 2);
    const size_t ro0 = (rowbase + r0g) * CDIM + h * DH;
    const size_t ro1 = (rowbase + r0g + 8) * CDIM + h * DH;
#pragma unroll
    for (int n = 0; n < 8; n++) {
        int c = n * 8 + (lane & 3) * 2;
        *(uint32_t*)&o16[ro0 + c] = pack_f16x2(o[n][0] * inv0, o[n][1] * inv0);
        *(uint32_t*)&o16[ro1 + c] = pack_f16x2(o[n][2] * inv1, o[n][3] * inv1);
    }
}

// ---------------------------------------------------------------------------
// Launch
// ---------------------------------------------------------------------------
extern "C" void kernel_launch(void* const* d_in, const int* in_sizes, int n_in,
                              void* d_out, int out_size) {
    const float* x      = (const float*)d_in[0];
    const float* w_qkv  = (const float*)d_in[1];
    const float* b_qkv  = (const float*)d_in[2];
    const float* w_proj = (const float*)d_in[3];
    const float* b_proj = (const float*)d_in[4];
    float* out = (float*)d_out;

    __half *qkv16, *x16, *wqT, *wpT, *attn16;
    cudaGetSymbolAddress((void**)&qkv16, g_qkv16);
    cudaGetSymbolAddress((void**)&x16, g_x16);
    cudaGetSymbolAddress((void**)&wqT, g_wqkvT);
    cudaGetSymbolAddress((void**)&wpT, g_wprojT);
    cudaGetSymbolAddress((void**)&attn16, g_attn16);

    cudaFuncSetAttribute(gemm_hmma_f16_kernel,
                         cudaFuncAttributeMaxDynamicSharedMemorySize, (int)GEMM_SMEM);
    cudaFuncSetAttribute(flash_attn_f16_kernel,
                         cudaFuncAttributeMaxDynamicSharedMemorySize, (int)ATT_SMEM);

    // 0) operand conversion
    {
        int n4 = MROWS * CDIM / 4;
        conv_f16_kernel<<<(n4 + 255) / 256, 256>>>(x, x16, n4);
        dim3 blk(32, 8);
        convT_f16_kernel<<<dim3(C3 / 32, CDIM / 32), blk>>>(w_qkv, wqT, CDIM, C3);
        convT_f16_kernel<<<dim3(CDIM / 32, CDIM / 32), blk>>>(w_proj, wpT, CDIM, CDIM);
    }

    // 1) QKV projection -> fp16 (Q pre-scaled by 0.125*log2e)
    gemm_hmma_f16_kernel<<<dim3(C3 / 128, MROWS / 128), 256, GEMM_SMEM>>>(
        x16, wqT, b_qkv, nullptr, qkv16, MROWS, C3, CDIM, 1, CDIM);

    // 2) fp16 flash attention -> fp16
    flash_attn_f16_kernel<<<dim3(T_SEQ / 128, BATCH * NH), 256, ATT_SMEM>>>(
        qkv16, attn16);

    // 3) Output projection -> fp32 d_out
    gemm_hmma_f16_kernel<<<dim3(CDIM / 128, MROWS / 128), 256, GEMM_SMEM>>>(
        attn16, wpT, b_proj, out, nullptr, MROWS, CDIM, CDIM, 0, 0);
}